// round 12
// baseline (speedup 1.0000x reference)
#include <cuda_runtime.h>
#include <math.h>
#include <stdint.h>

// ---------------- problem constants ----------------
#define B_SZ    2
#define SEQ_L   2048
#define D_MODEL 1024
#define D_STATE 16
#define D_CONV  4
#define D_INNER 2048
#define DT_RANK 64
#define M_TOTAL (B_SZ * SEQ_L)   // 4096 tokens
#define XBC_LD  128              // padded row stride for xbc / wcat

// ---------------- scratch (device globals; no allocation allowed) ----------------
__device__ float g_xz[(size_t)M_TOTAL * 2 * D_INNER];   // in_proj output: [4096, 4096] (x_in | z)
__device__ float g_xconv[(size_t)M_TOTAL * D_INNER];    // conv+silu output
__device__ float g_xbc[(size_t)M_TOTAL * XBC_LD];       // [xdt(64) | B(16) | C(16) | pad(32)]
__device__ float g_dt[(size_t)M_TOTAL * D_INNER];       // softplus dt
__device__ float g_y[(size_t)M_TOTAL * D_INNER];        // scan output (gated)
__device__ float g_wcat[XBC_LD * D_INNER];              // [x_proj_w; B_proj_w; C_proj_w; zeros]

// ---------------- tf32 helpers ----------------
__device__ __forceinline__ uint32_t f2tf32(float f) {
    uint32_t r;
    asm("cvt.rna.tf32.f32 %0, %1;" : "=r"(r) : "f"(f));
    return r;
}

__device__ __forceinline__ void mma_tf32(float* c, const uint32_t* a, const uint32_t* b) {
    asm volatile(
        "mma.sync.aligned.m16n8k8.row.col.f32.tf32.tf32.f32 "
        "{%0,%1,%2,%3},{%4,%5,%6,%7},{%8,%9},{%0,%1,%2,%3};"
        : "+f"(c[0]), "+f"(c[1]), "+f"(c[2]), "+f"(c[3])
        : "r"(a[0]), "r"(a[1]), "r"(a[2]), "r"(a[3]), "r"(b[0]), "r"(b[1]));
}

__device__ __forceinline__ void cp16(uint32_t dst, const void* src) {
    asm volatile("cp.async.cg.shared.global [%0], [%1], 16;" :: "r"(dst), "l"(src));
}
__device__ __forceinline__ void cp_commit() {
    asm volatile("cp.async.commit_group;" ::: "memory");
}
template<int N>
__device__ __forceinline__ void cp_wait() {
    asm volatile("cp.async.wait_group %0;" :: "n"(N) : "memory");
}

// ================= tf32 mma.sync GEMM, cp.async multistage =================
// C[m,n] = act( sum_k A[m,k] * W[n,k] (+ bias[n]) )
// BM = 128, BN = 64, BK = 16, STAGES = 3. 256 threads = 8 warps (2 m x 4 n).
// Warp tile 64x16 -> 4 m16-tiles x 2 n8-tiles = 8 mma per k8 step.
// 4 blocks/SM (launch_bounds): smem 45KB/block, regs capped at 64.
// smem m-major, pitch 20 words; fragment LDS.32 pattern (g*20+tg) mod 32
// covers all banks. tf32 conversion (cvt.rna) in the consumer.
// ACT: 0 = none, 1 = softplus(v + bias[n])
#define PITCH  20
#define STAGES 3
#define STW_A  (128 * PITCH)
#define STW_B  (64 * PITCH)
#define GEMM_SMEM (STAGES * (STW_A + STW_B) * 4)   // 46080 bytes

template<int ACT>
__global__ __launch_bounds__(256, 4)
void tc_gemm(const float* __restrict__ A, int lda,
             const float* __restrict__ W, int ldw,
             const float* __restrict__ bias,
             float* __restrict__ C, int ldc, int K)
{
    extern __shared__ uint32_t sm[];

    const int tid  = threadIdx.x;
    const int wid  = tid >> 5;
    const int lane = tid & 31;
    const int g    = lane >> 2;       // group id 0..7
    const int tg   = lane & 3;        // thread-in-group 0..3
    const int wm   = (wid & 1) * 64;  // warp m offset
    const int wn   = (wid >> 1) * 16; // warp n offset
    const int m0   = blockIdx.y * 128;
    const int n0   = blockIdx.x * 64;

    // loader: A rows {t>>2, (t>>2)+64} (2 cp16), B row t>>2 (1 cp16); quad t&3
    const int c4 = tid & 3;
    const int r0 = tid >> 2;          // 0..63
    const float* aP = A + (size_t)(m0 + r0) * lda + c4 * 4;
    const float* wP = W + (size_t)(n0 + r0) * ldw + c4 * 4;
    const size_t aStep = (size_t)64 * lda;

    uint32_t sbase;
    asm("{ .reg .u64 t; cvta.to.shared.u64 t, %1; cvt.u32.u64 %0, t; }" : "=r"(sbase) : "l"(sm));
    const uint32_t dOffA0 = (uint32_t)(r0 * PITCH + c4 * 4) * 4;          // bytes
    const uint32_t dOffA1 = (uint32_t)((r0 + 64) * PITCH + c4 * 4) * 4;
    const uint32_t dOffB  = dOffA0;

    const int KC = K / 16;

    // prologue: issue chunks 0..STAGES-2 (buffers 0..STAGES-2)
#pragma unroll
    for (int s = 0; s < STAGES - 1; s++) {
        if (s < KC) {
            const uint32_t aB = sbase + (uint32_t)(s * STW_A) * 4;
            const uint32_t bB = sbase + (uint32_t)(STAGES * STW_A + s * STW_B) * 4;
            const int k0 = s * 16;
            cp16(aB + dOffA0, aP + k0);  cp16(aB + dOffA1, aP + aStep + k0);
            cp16(bB + dOffB, wP + k0);
        }
        cp_commit();
    }

    float acc[4][2][4];
#pragma unroll
    for (int i = 0; i < 4; i++)
#pragma unroll
        for (int j = 0; j < 2; j++)
#pragma unroll
            for (int q = 0; q < 4; q++) acc[i][j][q] = 0.f;

    int bc = 0;                 // consume buffer = c % STAGES
    int bi = STAGES - 1;        // issue buffer   = (c + STAGES-1) % STAGES

    for (int c = 0; c < KC; c++) {
        cp_wait<STAGES - 2>();        // chunk c landed
        __syncthreads();              // all threads see it; reuse buffer drained

        // issue chunk c+STAGES-1 into buffer bi
        {
            const int cn = c + STAGES - 1;
            if (cn < KC) {
                const uint32_t aB = sbase + (uint32_t)(bi * STW_A) * 4;
                const uint32_t bB = sbase + (uint32_t)(STAGES * STW_A + bi * STW_B) * 4;
                const int k0 = cn * 16;
                cp16(aB + dOffA0, aP + k0);  cp16(aB + dOffA1, aP + aStep + k0);
                cp16(bB + dOffB, wP + k0);
            }
            cp_commit();
        }

        // consume chunk c from buffer bc
        const float* sAw = (const float*)(sm + bc * STW_A) + (wm + g) * PITCH + tg;
        const float* sBw = (const float*)(sm + STAGES * STW_A + bc * STW_B) + (wn + g) * PITCH + tg;
#pragma unroll
        for (int ks = 0; ks < 2; ks++) {
            const int kb = ks * 8;
            uint32_t af[4][4], bf[2][2];
#pragma unroll
            for (int mt = 0; mt < 4; mt++) {
                af[mt][0] = f2tf32(sAw[mt * 16 * PITCH + kb]);
                af[mt][1] = f2tf32(sAw[mt * 16 * PITCH + 8 * PITCH + kb]);
                af[mt][2] = f2tf32(sAw[mt * 16 * PITCH + kb + 4]);
                af[mt][3] = f2tf32(sAw[mt * 16 * PITCH + 8 * PITCH + kb + 4]);
            }
#pragma unroll
            for (int nt = 0; nt < 2; nt++) {
                bf[nt][0] = f2tf32(sBw[nt * 8 * PITCH + kb]);
                bf[nt][1] = f2tf32(sBw[nt * 8 * PITCH + kb + 4]);
            }
#pragma unroll
            for (int mt = 0; mt < 4; mt++)
#pragma unroll
                for (int nt = 0; nt < 2; nt++)
                    mma_tf32(acc[mt][nt], af[mt], bf[nt]);
        }

        if (++bc == STAGES) bc = 0;
        if (++bi == STAGES) bi = 0;
    }

    // ---- epilogue: registers -> gmem (float2 per fragment row) ----
#pragma unroll
    for (int mt = 0; mt < 4; mt++) {
#pragma unroll
        for (int nt = 0; nt < 2; nt++) {
            const int row = m0 + wm + mt * 16 + g;
            const int col = n0 + wn + nt * 8 + 2 * tg;
            float v0 = acc[mt][nt][0], v1 = acc[mt][nt][1];
            float v2 = acc[mt][nt][2], v3 = acc[mt][nt][3];
            if (ACT == 1) {
                float b0 = bias[col], b1 = bias[col + 1];
                v0 += b0; v1 += b1; v2 += b0; v3 += b1;
                v0 = (v0 > 20.f) ? v0 : __logf(1.f + __expf(v0));   // fast softplus
                v1 = (v1 > 20.f) ? v1 : __logf(1.f + __expf(v1));
                v2 = (v2 > 20.f) ? v2 : __logf(1.f + __expf(v2));
                v3 = (v3 > 20.f) ? v3 : __logf(1.f + __expf(v3));
            }
            *(float2*)(C + (size_t)row * ldc + col)       = make_float2(v0, v1);
            *(float2*)(C + (size_t)(row + 8) * ldc + col) = make_float2(v2, v3);
        }
    }
}

// ---------------- causal depthwise conv (width 4) + SiLU ----------------
__global__ void conv_silu_kernel(const float* __restrict__ conv_w,
                                 const float* __restrict__ conv_b)
{
    int idx = blockIdx.x * blockDim.x + threadIdx.x;
    if (idx >= M_TOTAL * D_INNER) return;
    int d  = idx % D_INNER;
    int ml = idx / D_INNER;      // b*L + l
    int l  = ml % SEQ_L;

    float acc = conv_b[d];
    const float* w = conv_w + d * D_CONV;
#pragma unroll
    for (int j = 0; j < D_CONV; j++) {
        int li = l - (D_CONV - 1) + j;
        if (li >= 0)
            acc = fmaf(w[j], g_xz[(size_t)(ml - (D_CONV - 1) + j) * (2 * D_INNER) + d], acc);
    }
    g_xconv[idx] = acc / (1.f + __expf(-acc));   // silu
}

// ---------------- selective scan (+ D skip + z gating) ----------------
// 8 channels per warp, 4 lanes per channel, 4 states per lane. 512 warps,
// launched as 512 blocks x 32 threads so all 148 SMs are busy.
// float4 loads for A/B/C; 2-deep software pipeline; 2-shfl reduction.
__global__ void scan_kernel(const float* __restrict__ A_log,
                            const float* __restrict__ Dp)
{
    const int gwarp = (blockIdx.x * blockDim.x + threadIdx.x) >> 5;  // 0..511
    const int lane  = threadIdx.x & 31;
    const int cw    = lane >> 2;          // channel within warp 0..7
    const int q     = lane & 3;           // state quad 0..3 (states q*4..q*4+3)
    const int ch    = gwarp * 8 + cw;     // 0..4095
    const int b     = ch / D_INNER;
    const int d     = ch % D_INNER;

    const float4 Alog4 = *(const float4*)(A_log + d * D_STATE + q * 4);
    const float A0 = -__expf(Alog4.x), A1 = -__expf(Alog4.y);
    const float A2 = -__expf(Alog4.z), A3 = -__expf(Alog4.w);
    const float Dv = Dp[d];

    const float* xrow  = g_xconv + (size_t)b * SEQ_L * D_INNER + d;
    const float* dtrow = g_dt    + (size_t)b * SEQ_L * D_INNER + d;
    const float* bcrow = g_xbc   + (size_t)b * SEQ_L * XBC_LD;
    const float* zrow  = g_xz    + (size_t)b * SEQ_L * (2 * D_INNER) + D_INNER + d;
    float*       yrow  = g_y     + (size_t)b * SEQ_L * D_INNER + d;

    float h0 = 0.f, h1 = 0.f, h2 = 0.f, h3 = 0.f;

    // pipeline slots for t and t+1
    float  xvA  = xrow[0],                    xvB  = xrow[D_INNER];
    float  dtA  = dtrow[0],                   dtB  = dtrow[D_INNER];
    float4 Bf4A = *(const float4*)(bcrow + DT_RANK + q * 4);
    float4 Cf4A = *(const float4*)(bcrow + DT_RANK + D_STATE + q * 4);
    float4 Bf4B = *(const float4*)(bcrow + XBC_LD + DT_RANK + q * 4);
    float4 Cf4B = *(const float4*)(bcrow + XBC_LD + DT_RANK + D_STATE + q * 4);
    float  zvA = 0.f, zvB = 0.f;
    if (q == 0) { zvA = zrow[0]; zvB = zrow[2 * D_INNER]; }

#pragma unroll 1
    for (int t = 0; t < SEQ_L; t += 2) {
        // prefetch t+2 / t+3 (clamped)
        const int t2 = (t + 2 < SEQ_L) ? t + 2 : SEQ_L - 1;
        const int t3 = (t + 3 < SEQ_L) ? t + 3 : SEQ_L - 1;
        float  xv2  = xrow [(size_t)t2 * D_INNER];
        float  dt2  = dtrow[(size_t)t2 * D_INNER];
        float4 Bf42 = *(const float4*)(bcrow + t2 * XBC_LD + DT_RANK + q * 4);
        float4 Cf42 = *(const float4*)(bcrow + t2 * XBC_LD + DT_RANK + D_STATE + q * 4);
        float  xv3  = xrow [(size_t)t3 * D_INNER];
        float  dt3  = dtrow[(size_t)t3 * D_INNER];
        float4 Bf43 = *(const float4*)(bcrow + t3 * XBC_LD + DT_RANK + q * 4);
        float4 Cf43 = *(const float4*)(bcrow + t3 * XBC_LD + DT_RANK + D_STATE + q * 4);
        float  zv2 = 0.f, zv3 = 0.f;
        if (q == 0) { zv2 = zrow[(size_t)t2 * 2 * D_INNER]; zv3 = zrow[(size_t)t3 * 2 * D_INNER]; }

        // ---- step t ----
        h0 = fmaf(dtA, fmaf(A0, h0, Bf4A.x * xvA), h0);
        h1 = fmaf(dtA, fmaf(A1, h1, Bf4A.y * xvA), h1);
        h2 = fmaf(dtA, fmaf(A2, h2, Bf4A.z * xvA), h2);
        h3 = fmaf(dtA, fmaf(A3, h3, Bf4A.w * xvA), h3);
        {
            float p = fmaf(h3, Cf4A.w, fmaf(h2, Cf4A.z, fmaf(h1, Cf4A.y, h0 * Cf4A.x)));
            p += __shfl_xor_sync(0xffffffffu, p, 1);
            p += __shfl_xor_sync(0xffffffffu, p, 2);
            if (q == 0) {
                float y = fmaf(Dv, xvA, p);
                y *= zvA / (1.f + __expf(-zvA));
                yrow[(size_t)t * D_INNER] = y;
            }
        }

        // ---- step t+1 ----
        h0 = fmaf(dtB, fmaf(A0, h0, Bf4B.x * xvB), h0);
        h1 = fmaf(dtB, fmaf(A1, h1, Bf4B.y * xvB), h1);
        h2 = fmaf(dtB, fmaf(A2, h2, Bf4B.z * xvB), h2);
        h3 = fmaf(dtB, fmaf(A3, h3, Bf4B.w * xvB), h3);
        {
            float p = fmaf(h3, Cf4B.w, fmaf(h2, Cf4B.z, fmaf(h1, Cf4B.y, h0 * Cf4B.x)));
            p += __shfl_xor_sync(0xffffffffu, p, 1);
            p += __shfl_xor_sync(0xffffffffu, p, 2);
            if (q == 0) {
                float y = fmaf(Dv, xvB, p);
                y *= zvB / (1.f + __expf(-zvB));
                yrow[(size_t)(t + 1) * D_INNER] = y;
            }
        }

        xvA = xv2; dtA = dt2; Bf4A = Bf42; Cf4A = Cf42; zvA = zv2;
        xvB = xv3; dtB = dt3; Bf4B = Bf43; Cf4B = Cf43; zvB = zv3;
    }
}

// ---------------- launch ----------------
extern "C" void kernel_launch(void* const* d_in, const int* in_sizes, int n_in,
                              void* d_out, int out_size)
{
    const float* x          = (const float*)d_in[0];
    const float* in_proj_w  = (const float*)d_in[1];
    const float* conv_w     = (const float*)d_in[2];
    const float* conv_b     = (const float*)d_in[3];
    const float* A_log      = (const float*)d_in[4];
    const float* Dp         = (const float*)d_in[5];
    const float* dt_proj_w  = (const float*)d_in[6];
    const float* dt_proj_b  = (const float*)d_in[7];
    const float* x_proj_w   = (const float*)d_in[8];
    const float* B_proj_w   = (const float*)d_in[9];
    const float* C_proj_w   = (const float*)d_in[10];
    const float* out_proj_w = (const float*)d_in[11];
    float* out = (float*)d_out;

    // resolve scratch addresses
    float *xz, *xconv, *xbc, *dt, *y, *wcat;
    cudaGetSymbolAddress((void**)&xz,    g_xz);
    cudaGetSymbolAddress((void**)&xconv, g_xconv);
    cudaGetSymbolAddress((void**)&xbc,   g_xbc);
    cudaGetSymbolAddress((void**)&dt,    g_dt);
    cudaGetSymbolAddress((void**)&y,     g_y);
    cudaGetSymbolAddress((void**)&wcat,  g_wcat);

    cudaFuncSetAttribute(tc_gemm<0>, cudaFuncAttributeMaxDynamicSharedMemorySize, GEMM_SMEM);
    cudaFuncSetAttribute(tc_gemm<1>, cudaFuncAttributeMaxDynamicSharedMemorySize, GEMM_SMEM);

    // pack [x_proj_w; B_proj_w; C_proj_w] -> g_wcat rows 0..95 (rows 96..127 stay zero)
    cudaMemcpyToSymbolAsync(g_wcat, x_proj_w, (size_t)DT_RANK * D_INNER * sizeof(float),
                            0, cudaMemcpyDeviceToDevice, 0);
    cudaMemcpyToSymbolAsync(g_wcat, B_proj_w, (size_t)D_STATE * D_INNER * sizeof(float),
                            (size_t)DT_RANK * D_INNER * sizeof(float), cudaMemcpyDeviceToDevice, 0);
    cudaMemcpyToSymbolAsync(g_wcat, C_proj_w, (size_t)D_STATE * D_INNER * sizeof(float),
                            (size_t)(DT_RANK + D_STATE) * D_INNER * sizeof(float), cudaMemcpyDeviceToDevice, 0);

    // 1) in_proj: xz = x @ in_proj_w^T   (M=4096, N=4096, K=1024)
    {
        dim3 grid(2 * D_INNER / 64, M_TOTAL / 128);
        tc_gemm<0><<<grid, 256, GEMM_SMEM>>>(x, D_MODEL, in_proj_w, D_MODEL, nullptr,
                                             xz, 2 * D_INNER, D_MODEL);
    }

    // 2) causal depthwise conv + silu -> g_xconv
    {
        int n = M_TOTAL * D_INNER;
        conv_silu_kernel<<<(n + 255) / 256, 256>>>(conv_w, conv_b);
    }

    // 3) fused x/B/C projection: xbc = xconv @ wcat^T  (M=4096, N=128(pad), K=2048)
    {
        dim3 grid(XBC_LD / 64, M_TOTAL / 128);
        tc_gemm<0><<<grid, 256, GEMM_SMEM>>>(xconv, D_INNER, wcat, D_INNER, nullptr,
                                             xbc, XBC_LD, D_INNER);
    }

    // 4) dt = softplus(xbc[:, :64] @ dt_proj_w^T + dt_proj_b)  (M=4096, N=2048, K=64)
    {
        dim3 grid(D_INNER / 64, M_TOTAL / 128);
        tc_gemm<1><<<grid, 256, GEMM_SMEM>>>(xbc, XBC_LD, dt_proj_w, DT_RANK, dt_proj_b,
                                             dt, D_INNER, DT_RANK);
    }

    // 5) selective scan + D skip + silu(z) gating -> g_y  (512 blocks: all SMs busy)
    scan_kernel<<<512, 32>>>(A_log, Dp);

    // 6) out = y @ out_proj_w^T   (M=4096, N=1024, K=2048)
    {
        dim3 grid(D_MODEL / 64, M_TOTAL / 128);
        tc_gemm<0><<<grid, 256, GEMM_SMEM>>>(y, D_INNER, out_proj_w, D_INNER, nullptr,
                                             out, D_MODEL, D_INNER);
    }
}

// round 13
// speedup vs baseline: 1.1062x; 1.1062x over previous
#include <cuda_runtime.h>
#include <math.h>
#include <stdint.h>

// ---------------- problem constants ----------------
#define B_SZ    2
#define SEQ_L   2048
#define D_MODEL 1024
#define D_STATE 16
#define D_CONV  4
#define D_INNER 2048
#define DT_RANK 64
#define M_TOTAL (B_SZ * SEQ_L)   // 4096 tokens
#define XBC_LD  128              // padded row stride for xbc / wcat

// ---------------- scratch (device globals; no allocation allowed) ----------------
__device__ float g_xz[(size_t)M_TOTAL * 2 * D_INNER];   // in_proj output: [4096, 4096] (x_in | z)
__device__ float g_xconv[(size_t)M_TOTAL * D_INNER];    // conv+silu output
__device__ float g_xbc[(size_t)M_TOTAL * XBC_LD];       // [xdt(64) | B(16) | C(16) | pad(32)]
__device__ float g_dt[(size_t)M_TOTAL * D_INNER];       // softplus dt
__device__ float g_y[(size_t)M_TOTAL * D_INNER];        // scan output (gated)
__device__ float g_wcat[XBC_LD * D_INNER];              // [x_proj_w; B_proj_w; C_proj_w; zeros]

// ---------------- tf32 helpers ----------------
__device__ __forceinline__ uint32_t f2tf32(float f) {
    uint32_t r;
    asm("cvt.rna.tf32.f32 %0, %1;" : "=r"(r) : "f"(f));
    return r;
}

__device__ __forceinline__ void mma_tf32(float* c, const uint32_t* a, const uint32_t* b) {
    asm volatile(
        "mma.sync.aligned.m16n8k8.row.col.f32.tf32.tf32.f32 "
        "{%0,%1,%2,%3},{%4,%5,%6,%7},{%8,%9},{%0,%1,%2,%3};"
        : "+f"(c[0]), "+f"(c[1]), "+f"(c[2]), "+f"(c[3])
        : "r"(a[0]), "r"(a[1]), "r"(a[2]), "r"(a[3]), "r"(b[0]), "r"(b[1]));
}

__device__ __forceinline__ void cp16(uint32_t dst, const void* src) {
    asm volatile("cp.async.cg.shared.global [%0], [%1], 16;" :: "r"(dst), "l"(src));
}
__device__ __forceinline__ void cp_commit() {
    asm volatile("cp.async.commit_group;" ::: "memory");
}
template<int N>
__device__ __forceinline__ void cp_wait() {
    asm volatile("cp.async.wait_group %0;" :: "n"(N) : "memory");
}

// ================= tf32 mma.sync GEMM, cp.async multistage =================
// C[m,n] = act( sum_k A[m,k] * W[n,k] (+ bias[n]) )
// BM = 128, BN in {64,128,256}, BK = 16. 256 threads = 8 warps (2 m x 4 n).
// Warp tile 64 x (BN/4): NT = BN/32 n8-tiles per warp, 4 m16-tiles.
// BN=256: STAGES=3, 1 block/SM (acc 128 regs). BN=128: STAGES=4, 2 blocks/SM.
// BN=64: STAGES=4, 3 blocks/SM (the proven R10 shape).
// smem m-major, pitch 20 words; fragment LDS.32 pattern (g*20+tg) mod 32
// covers all 32 banks. tf32 conversion (cvt.rna) in the consumer.
// ACT: 0 = none, 1 = softplus(v + bias[n])
#define PITCH  20

template<int BN> struct GCfg {
    static constexpr int STAGES = (BN == 256) ? 3 : 4;
    static constexpr int MINB   = (BN == 256) ? 1 : ((BN == 64) ? 3 : 2);
    static constexpr int SMEM   = STAGES * (128 + BN) * PITCH * 4;
};

template<int BN, int ACT>
__global__ __launch_bounds__(256, GCfg<BN>::MINB)
void tc_gemm(const float* __restrict__ A, int lda,
             const float* __restrict__ W, int ldw,
             const float* __restrict__ bias,
             float* __restrict__ C, int ldc, int K)
{
    constexpr int NT     = BN / 32;         // n8 tiles per warp
    constexpr int STAGES = GCfg<BN>::STAGES;
    constexpr int STW_A  = 128 * PITCH;
    constexpr int STW_B  = BN * PITCH;
    constexpr int BJ     = BN / 64;         // B cp16 rows per thread

    extern __shared__ uint32_t sm[];

    const int tid  = threadIdx.x;
    const int wid  = tid >> 5;
    const int lane = tid & 31;
    const int g    = lane >> 2;       // group id 0..7
    const int tg   = lane & 3;        // thread-in-group 0..3
    const int wm   = (wid & 1) * 64;          // warp m offset
    const int wn   = (wid >> 1) * (BN / 4);   // warp n offset
    const int m0   = blockIdx.y * 128;
    const int n0   = blockIdx.x * BN;

    // loader: A rows {r0, r0+64}; B rows {r0 + 64*j, j<BJ}; float4 slot c4
    const int c4 = tid & 3;
    const int r0 = tid >> 2;          // 0..63
    const float* aP = A + (size_t)(m0 + r0) * lda + c4 * 4;
    const float* wP = W + (size_t)(n0 + r0) * ldw + c4 * 4;
    const size_t aStep = (size_t)64 * lda;
    const size_t wStep = (size_t)64 * ldw;

    uint32_t sbase;
    asm("{ .reg .u64 t; cvta.to.shared.u64 t, %1; cvt.u32.u64 %0, t; }" : "=r"(sbase) : "l"(sm));
    const uint32_t dOffA0 = (uint32_t)(r0 * PITCH + c4 * 4) * 4;          // bytes
    const uint32_t dOffA1 = (uint32_t)((r0 + 64) * PITCH + c4 * 4) * 4;

    const int KC = K / 16;

    // prologue: issue chunks 0..STAGES-2
#pragma unroll
    for (int s = 0; s < STAGES - 1; s++) {
        if (s < KC) {
            const uint32_t aB = sbase + (uint32_t)(s * STW_A) * 4;
            const uint32_t bB = sbase + (uint32_t)(STAGES * STW_A + s * STW_B) * 4;
            const int k0 = s * 16;
            cp16(aB + dOffA0, aP + k0);  cp16(aB + dOffA1, aP + aStep + k0);
#pragma unroll
            for (int j = 0; j < BJ; j++)
                cp16(bB + dOffA0 + (uint32_t)(j * 64 * PITCH * 4), wP + j * wStep + k0);
        }
        cp_commit();
    }

    float acc[4][NT][4];
#pragma unroll
    for (int i = 0; i < 4; i++)
#pragma unroll
        for (int j = 0; j < NT; j++)
#pragma unroll
            for (int q = 0; q < 4; q++) acc[i][j][q] = 0.f;

    int bc = 0;                 // consume buffer
    int bi = STAGES - 1;        // issue buffer

    for (int c = 0; c < KC; c++) {
        cp_wait<STAGES - 2>();
        __syncthreads();

        // issue chunk c+STAGES-1 into buffer bi
        {
            const int cn = c + STAGES - 1;
            if (cn < KC) {
                const uint32_t aB = sbase + (uint32_t)(bi * STW_A) * 4;
                const uint32_t bB = sbase + (uint32_t)(STAGES * STW_A + bi * STW_B) * 4;
                const int k0 = cn * 16;
                cp16(aB + dOffA0, aP + k0);  cp16(aB + dOffA1, aP + aStep + k0);
#pragma unroll
                for (int j = 0; j < BJ; j++)
                    cp16(bB + dOffA0 + (uint32_t)(j * 64 * PITCH * 4), wP + j * wStep + k0);
            }
            cp_commit();
        }

        // consume chunk c from buffer bc
        const float* sAw = (const float*)(sm + bc * STW_A) + (wm + g) * PITCH + tg;
        const float* sBw = (const float*)(sm + STAGES * STW_A + bc * STW_B) + (wn + g) * PITCH + tg;
#pragma unroll
        for (int ks = 0; ks < 2; ks++) {
            const int kb = ks * 8;
            uint32_t af[4][4], bf[NT][2];
#pragma unroll
            for (int mt = 0; mt < 4; mt++) {
                af[mt][0] = f2tf32(sAw[mt * 16 * PITCH + kb]);
                af[mt][1] = f2tf32(sAw[mt * 16 * PITCH + 8 * PITCH + kb]);
                af[mt][2] = f2tf32(sAw[mt * 16 * PITCH + kb + 4]);
                af[mt][3] = f2tf32(sAw[mt * 16 * PITCH + 8 * PITCH + kb + 4]);
            }
#pragma unroll
            for (int nt = 0; nt < NT; nt++) {
                bf[nt][0] = f2tf32(sBw[nt * 8 * PITCH + kb]);
                bf[nt][1] = f2tf32(sBw[nt * 8 * PITCH + kb + 4]);
            }
#pragma unroll
            for (int mt = 0; mt < 4; mt++)
#pragma unroll
                for (int nt = 0; nt < NT; nt++)
                    mma_tf32(acc[mt][nt], af[mt], bf[nt]);
        }

        if (++bc == STAGES) bc = 0;
        if (++bi == STAGES) bi = 0;
    }

    // ---- epilogue: registers -> gmem (float2 per fragment row) ----
#pragma unroll
    for (int mt = 0; mt < 4; mt++) {
#pragma unroll
        for (int nt = 0; nt < NT; nt++) {
            const int row = m0 + wm + mt * 16 + g;
            const int col = n0 + wn + nt * 8 + 2 * tg;
            float v0 = acc[mt][nt][0], v1 = acc[mt][nt][1];
            float v2 = acc[mt][nt][2], v3 = acc[mt][nt][3];
            if (ACT == 1) {
                float b0 = bias[col], b1 = bias[col + 1];
                v0 += b0; v1 += b1; v2 += b0; v3 += b1;
                v0 = (v0 > 20.f) ? v0 : __logf(1.f + __expf(v0));   // fast softplus
                v1 = (v1 > 20.f) ? v1 : __logf(1.f + __expf(v1));
                v2 = (v2 > 20.f) ? v2 : __logf(1.f + __expf(v2));
                v3 = (v3 > 20.f) ? v3 : __logf(1.f + __expf(v3));
            }
            *(float2*)(C + (size_t)row * ldc + col)       = make_float2(v0, v1);
            *(float2*)(C + (size_t)(row + 8) * ldc + col) = make_float2(v2, v3);
        }
    }
}

// ---------------- causal depthwise conv (width 4) + SiLU ----------------
__global__ void conv_silu_kernel(const float* __restrict__ conv_w,
                                 const float* __restrict__ conv_b)
{
    int idx = blockIdx.x * blockDim.x + threadIdx.x;
    if (idx >= M_TOTAL * D_INNER) return;
    int d  = idx % D_INNER;
    int ml = idx / D_INNER;      // b*L + l
    int l  = ml % SEQ_L;

    float acc = conv_b[d];
    const float* w = conv_w + d * D_CONV;
#pragma unroll
    for (int j = 0; j < D_CONV; j++) {
        int li = l - (D_CONV - 1) + j;
        if (li >= 0)
            acc = fmaf(w[j], g_xz[(size_t)(ml - (D_CONV - 1) + j) * (2 * D_INNER) + d], acc);
    }
    g_xconv[idx] = acc / (1.f + __expf(-acc));   // silu
}

// ---------------- selective scan (+ D skip + z gating) ----------------
// 8 channels per warp, 4 lanes per channel, 4 states per lane. 512 warps,
// launched as 512 blocks x 32 threads so all 148 SMs are busy.
// float4 loads for A/B/C; 2-deep software pipeline; 2-shfl reduction.
__global__ void scan_kernel(const float* __restrict__ A_log,
                            const float* __restrict__ Dp)
{
    const int gwarp = (blockIdx.x * blockDim.x + threadIdx.x) >> 5;  // 0..511
    const int lane  = threadIdx.x & 31;
    const int cw    = lane >> 2;          // channel within warp 0..7
    const int q     = lane & 3;           // state quad 0..3 (states q*4..q*4+3)
    const int ch    = gwarp * 8 + cw;     // 0..4095
    const int b     = ch / D_INNER;
    const int d     = ch % D_INNER;

    const float4 Alog4 = *(const float4*)(A_log + d * D_STATE + q * 4);
    const float A0 = -__expf(Alog4.x), A1 = -__expf(Alog4.y);
    const float A2 = -__expf(Alog4.z), A3 = -__expf(Alog4.w);
    const float Dv = Dp[d];

    const float* xrow  = g_xconv + (size_t)b * SEQ_L * D_INNER + d;
    const float* dtrow = g_dt    + (size_t)b * SEQ_L * D_INNER + d;
    const float* bcrow = g_xbc   + (size_t)b * SEQ_L * XBC_LD;
    const float* zrow  = g_xz    + (size_t)b * SEQ_L * (2 * D_INNER) + D_INNER + d;
    float*       yrow  = g_y     + (size_t)b * SEQ_L * D_INNER + d;

    float h0 = 0.f, h1 = 0.f, h2 = 0.f, h3 = 0.f;

    // pipeline slots for t and t+1
    float  xvA  = xrow[0],                    xvB  = xrow[D_INNER];
    float  dtA  = dtrow[0],                   dtB  = dtrow[D_INNER];
    float4 Bf4A = *(const float4*)(bcrow + DT_RANK + q * 4);
    float4 Cf4A = *(const float4*)(bcrow + DT_RANK + D_STATE + q * 4);
    float4 Bf4B = *(const float4*)(bcrow + XBC_LD + DT_RANK + q * 4);
    float4 Cf4B = *(const float4*)(bcrow + XBC_LD + DT_RANK + D_STATE + q * 4);
    float  zvA = 0.f, zvB = 0.f;
    if (q == 0) { zvA = zrow[0]; zvB = zrow[2 * D_INNER]; }

#pragma unroll 1
    for (int t = 0; t < SEQ_L; t += 2) {
        // prefetch t+2 / t+3 (clamped)
        const int t2 = (t + 2 < SEQ_L) ? t + 2 : SEQ_L - 1;
        const int t3 = (t + 3 < SEQ_L) ? t + 3 : SEQ_L - 1;
        float  xv2  = xrow [(size_t)t2 * D_INNER];
        float  dt2  = dtrow[(size_t)t2 * D_INNER];
        float4 Bf42 = *(const float4*)(bcrow + t2 * XBC_LD + DT_RANK + q * 4);
        float4 Cf42 = *(const float4*)(bcrow + t2 * XBC_LD + DT_RANK + D_STATE + q * 4);
        float  xv3  = xrow [(size_t)t3 * D_INNER];
        float  dt3  = dtrow[(size_t)t3 * D_INNER];
        float4 Bf43 = *(const float4*)(bcrow + t3 * XBC_LD + DT_RANK + q * 4);
        float4 Cf43 = *(const float4*)(bcrow + t3 * XBC_LD + DT_RANK + D_STATE + q * 4);
        float  zv2 = 0.f, zv3 = 0.f;
        if (q == 0) { zv2 = zrow[(size_t)t2 * 2 * D_INNER]; zv3 = zrow[(size_t)t3 * 2 * D_INNER]; }

        // ---- step t ----
        h0 = fmaf(dtA, fmaf(A0, h0, Bf4A.x * xvA), h0);
        h1 = fmaf(dtA, fmaf(A1, h1, Bf4A.y * xvA), h1);
        h2 = fmaf(dtA, fmaf(A2, h2, Bf4A.z * xvA), h2);
        h3 = fmaf(dtA, fmaf(A3, h3, Bf4A.w * xvA), h3);
        {
            float p = fmaf(h3, Cf4A.w, fmaf(h2, Cf4A.z, fmaf(h1, Cf4A.y, h0 * Cf4A.x)));
            p += __shfl_xor_sync(0xffffffffu, p, 1);
            p += __shfl_xor_sync(0xffffffffu, p, 2);
            if (q == 0) {
                float y = fmaf(Dv, xvA, p);
                y *= zvA / (1.f + __expf(-zvA));
                yrow[(size_t)t * D_INNER] = y;
            }
        }

        // ---- step t+1 ----
        h0 = fmaf(dtB, fmaf(A0, h0, Bf4B.x * xvB), h0);
        h1 = fmaf(dtB, fmaf(A1, h1, Bf4B.y * xvB), h1);
        h2 = fmaf(dtB, fmaf(A2, h2, Bf4B.z * xvB), h2);
        h3 = fmaf(dtB, fmaf(A3, h3, Bf4B.w * xvB), h3);
        {
            float p = fmaf(h3, Cf4B.w, fmaf(h2, Cf4B.z, fmaf(h1, Cf4B.y, h0 * Cf4B.x)));
            p += __shfl_xor_sync(0xffffffffu, p, 1);
            p += __shfl_xor_sync(0xffffffffu, p, 2);
            if (q == 0) {
                float y = fmaf(Dv, xvB, p);
                y *= zvB / (1.f + __expf(-zvB));
                yrow[(size_t)(t + 1) * D_INNER] = y;
            }
        }

        xvA = xv2; dtA = dt2; Bf4A = Bf42; Cf4A = Cf42; zvA = zv2;
        xvB = xv3; dtB = dt3; Bf4B = Bf43; Cf4B = Cf43; zvB = zv3;
    }
}

// ---------------- launch ----------------
extern "C" void kernel_launch(void* const* d_in, const int* in_sizes, int n_in,
                              void* d_out, int out_size)
{
    const float* x          = (const float*)d_in[0];
    const float* in_proj_w  = (const float*)d_in[1];
    const float* conv_w     = (const float*)d_in[2];
    const float* conv_b     = (const float*)d_in[3];
    const float* A_log      = (const float*)d_in[4];
    const float* Dp         = (const float*)d_in[5];
    const float* dt_proj_w  = (const float*)d_in[6];
    const float* dt_proj_b  = (const float*)d_in[7];
    const float* x_proj_w   = (const float*)d_in[8];
    const float* B_proj_w   = (const float*)d_in[9];
    const float* C_proj_w   = (const float*)d_in[10];
    const float* out_proj_w = (const float*)d_in[11];
    float* out = (float*)d_out;

    // resolve scratch addresses
    float *xz, *xconv, *xbc, *dt, *y, *wcat;
    cudaGetSymbolAddress((void**)&xz,    g_xz);
    cudaGetSymbolAddress((void**)&xconv, g_xconv);
    cudaGetSymbolAddress((void**)&xbc,   g_xbc);
    cudaGetSymbolAddress((void**)&dt,    g_dt);
    cudaGetSymbolAddress((void**)&y,     g_y);
    cudaGetSymbolAddress((void**)&wcat,  g_wcat);

    cudaFuncSetAttribute(tc_gemm<256, 0>, cudaFuncAttributeMaxDynamicSharedMemorySize, GCfg<256>::SMEM);
    cudaFuncSetAttribute(tc_gemm<128, 0>, cudaFuncAttributeMaxDynamicSharedMemorySize, GCfg<128>::SMEM);
    cudaFuncSetAttribute(tc_gemm<128, 1>, cudaFuncAttributeMaxDynamicSharedMemorySize, GCfg<128>::SMEM);
    cudaFuncSetAttribute(tc_gemm<64, 0>,  cudaFuncAttributeMaxDynamicSharedMemorySize, GCfg<64>::SMEM);

    // pack [x_proj_w; B_proj_w; C_proj_w] -> g_wcat rows 0..95 (rows 96..127 stay zero)
    cudaMemcpyToSymbolAsync(g_wcat, x_proj_w, (size_t)DT_RANK * D_INNER * sizeof(float),
                            0, cudaMemcpyDeviceToDevice, 0);
    cudaMemcpyToSymbolAsync(g_wcat, B_proj_w, (size_t)D_STATE * D_INNER * sizeof(float),
                            (size_t)DT_RANK * D_INNER * sizeof(float), cudaMemcpyDeviceToDevice, 0);
    cudaMemcpyToSymbolAsync(g_wcat, C_proj_w, (size_t)D_STATE * D_INNER * sizeof(float),
                            (size_t)(DT_RANK + D_STATE) * D_INNER * sizeof(float), cudaMemcpyDeviceToDevice, 0);

    // 1) in_proj: xz = x @ in_proj_w^T   (M=4096, N=4096, K=1024)  [BN=256]
    {
        dim3 grid(2 * D_INNER / 256, M_TOTAL / 128);
        tc_gemm<256, 0><<<grid, 256, GCfg<256>::SMEM>>>(
            x, D_MODEL, in_proj_w, D_MODEL, nullptr, xz, 2 * D_INNER, D_MODEL);
    }

    // 2) causal depthwise conv + silu -> g_xconv
    {
        int n = M_TOTAL * D_INNER;
        conv_silu_kernel<<<(n + 255) / 256, 256>>>(conv_w, conv_b);
    }

    // 3) fused x/B/C projection: xbc = xconv @ wcat^T  (M=4096, N=128(pad), K=2048) [BN=64]
    {
        dim3 grid(XBC_LD / 64, M_TOTAL / 128);
        tc_gemm<64, 0><<<grid, 256, GCfg<64>::SMEM>>>(
            xconv, D_INNER, wcat, D_INNER, nullptr, xbc, XBC_LD, D_INNER);
    }

    // 4) dt = softplus(xbc[:, :64] @ dt_proj_w^T + dt_proj_b)  (M=4096, N=2048, K=64) [BN=128]
    {
        dim3 grid(D_INNER / 128, M_TOTAL / 128);
        tc_gemm<128, 1><<<grid, 256, GCfg<128>::SMEM>>>(
            xbc, XBC_LD, dt_proj_w, DT_RANK, dt_proj_b, dt, D_INNER, DT_RANK);
    }

    // 5) selective scan + D skip + silu(z) gating -> g_y  (512 blocks: all SMs busy)
    scan_kernel<<<512, 32>>>(A_log, Dp);

    // 6) out = y @ out_proj_w^T   (M=4096, N=1024, K=2048) [BN=128]
    {
        dim3 grid(D_MODEL / 128, M_TOTAL / 128);
        tc_gemm<128, 0><<<grid, 256, GCfg<128>::SMEM>>>(
            y, D_INNER, out_proj_w, D_INNER, nullptr, out, D_MODEL, D_INNER);
    }
}

// round 14
// speedup vs baseline: 1.3547x; 1.2246x over previous
#include <cuda_runtime.h>
#include <cuda_fp16.h>
#include <math.h>
#include <stdint.h>

// ---------------- problem constants ----------------
#define B_SZ    2
#define SEQ_L   2048
#define D_MODEL 1024
#define D_STATE 16
#define D_CONV  4
#define D_INNER 2048
#define DT_RANK 64
#define M_TOTAL (B_SZ * SEQ_L)   // 4096 tokens
#define XBC_LD  128              // padded row stride for xbc / wcat

// ---------------- scratch (device globals; no allocation allowed) ----------------
__device__ float  g_xz[(size_t)M_TOTAL * 2 * D_INNER];  // in_proj output (x_in | z), fp32
__device__ float  g_xconv[(size_t)M_TOTAL * D_INNER];   // conv+silu output, fp32 (scan)
__device__ __half g_xconv_h[(size_t)M_TOTAL * D_INNER]; // conv+silu output, fp16 (xbc GEMM)
__device__ float  g_xbc[(size_t)M_TOTAL * XBC_LD];      // [xdt|B|C|pad] fp32 (scan)
__device__ __half g_xbc_h[(size_t)M_TOTAL * XBC_LD];    // fp16 copy (dt GEMM A)
__device__ float  g_dt[(size_t)M_TOTAL * D_INNER];      // softplus dt, fp32 (scan)
__device__ __half g_y_h[(size_t)M_TOTAL * D_INNER];     // scan output, fp16 (out_proj A)
__device__ float  g_wcat[XBC_LD * D_INNER];             // [x_proj_w; B_proj_w; C_proj_w; 0]
__device__ __half g_wcat_h[XBC_LD * D_INNER];
__device__ __half g_x_h[(size_t)M_TOTAL * D_MODEL];
__device__ __half g_win_h[(size_t)2 * D_INNER * D_MODEL];
__device__ __half g_wdt_h[(size_t)D_INNER * DT_RANK];
__device__ __half g_wout_h[(size_t)D_MODEL * D_INNER];

// ---------------- helpers ----------------
__device__ __forceinline__ void mma_f16(float* c, const uint32_t* a, const uint32_t* b) {
    asm volatile(
        "mma.sync.aligned.m16n8k16.row.col.f32.f16.f16.f32 "
        "{%0,%1,%2,%3},{%4,%5,%6,%7},{%8,%9},{%0,%1,%2,%3};"
        : "+f"(c[0]), "+f"(c[1]), "+f"(c[2]), "+f"(c[3])
        : "r"(a[0]), "r"(a[1]), "r"(a[2]), "r"(a[3]), "r"(b[0]), "r"(b[1]));
}

__device__ __forceinline__ void cp16(uint32_t dst, const void* src) {
    asm volatile("cp.async.cg.shared.global [%0], [%1], 16;" :: "r"(dst), "l"(src));
}
__device__ __forceinline__ void cp_commit() {
    asm volatile("cp.async.commit_group;" ::: "memory");
}
template<int N>
__device__ __forceinline__ void cp_wait() {
    asm volatile("cp.async.wait_group %0;" :: "n"(N) : "memory");
}

// ---------------- fp32 -> fp16 conversion ----------------
__global__ void cvt_f16_kernel(const float* __restrict__ src, __half* __restrict__ dst, int n4)
{
    int i = blockIdx.x * blockDim.x + threadIdx.x;
    if (i >= n4) return;
    float4 v = ((const float4*)src)[i];
    ((__half2*)dst)[2 * i + 0] = __floats2half2_rn(v.x, v.y);
    ((__half2*)dst)[2 * i + 1] = __floats2half2_rn(v.z, v.w);
}

// ================= fp16 mma.sync GEMM, cp.async multistage =================
// C[m,n] = act( sum_k A[m,k] * W[n,k] (+ bias[n]) ), A/W fp16, accum fp32.
// BM = 128, BN in {64,128,256}, BK = 32 halfs (64B/row). 256 threads = 8 warps
// (2 m x 4 n). Warp tile 64 x (BN/4): NT = BN/32 n8-tiles, 4 m16-tiles,
// mma.m16n8k16 -> 2 k-steps per chunk.
// smem m-major, row = 16 words (+4 pad = PITCH 20): fragment LDS.32 pattern
// (g*20+tg) mod 32 covers all 32 banks; same addresses as the tf32 version
// but each word carries 2 halfs (2x K per LDS/MMA).
// ACT: 1 = softplus(v + bias[n]).  DUAL: also write fp16 copy to Ch.
#define PITCH  20

template<int BN> struct GCfg {
    static constexpr int STAGES = (BN == 256) ? 3 : 4;
    static constexpr int MINB   = (BN == 256) ? 1 : ((BN == 64) ? 3 : 2);
    static constexpr int SMEM   = STAGES * (128 + BN) * PITCH * 4;
};

template<int BN, int ACT, int DUAL>
__global__ __launch_bounds__(256, GCfg<BN>::MINB)
void tc_gemm(const __half* __restrict__ A, int lda,
             const __half* __restrict__ W, int ldw,
             const float* __restrict__ bias,
             float* __restrict__ C, __half* __restrict__ Ch, int ldc, int K)
{
    constexpr int NT     = BN / 32;
    constexpr int STAGES = GCfg<BN>::STAGES;
    constexpr int STW_A  = 128 * PITCH;        // words
    constexpr int STW_B  = BN * PITCH;
    constexpr int BJ     = BN / 64;

    extern __shared__ uint32_t sm[];

    const int tid  = threadIdx.x;
    const int wid  = tid >> 5;
    const int lane = tid & 31;
    const int g    = lane >> 2;
    const int tg   = lane & 3;
    const int wm   = (wid & 1) * 64;
    const int wn   = (wid >> 1) * (BN / 4);
    const int m0   = blockIdx.y * 128;
    const int n0   = blockIdx.x * BN;

    // loader: A rows {r0, r0+64}; B rows {r0 + 64*j}; 16B slot c4 (8 halfs)
    const int c4 = tid & 3;
    const int r0 = tid >> 2;
    const __half* aP = A + (size_t)(m0 + r0) * lda + c4 * 8;
    const __half* wP = W + (size_t)(n0 + r0) * ldw + c4 * 8;
    const size_t aStep = (size_t)64 * lda;
    const size_t wStep = (size_t)64 * ldw;

    uint32_t sbase;
    asm("{ .reg .u64 t; cvta.to.shared.u64 t, %1; cvt.u32.u64 %0, t; }" : "=r"(sbase) : "l"(sm));
    const uint32_t dOffA0 = (uint32_t)(r0 * PITCH + c4 * 4) * 4;          // bytes
    const uint32_t dOffA1 = (uint32_t)((r0 + 64) * PITCH + c4 * 4) * 4;

    const int KC = K / 32;

    // prologue
#pragma unroll
    for (int s = 0; s < STAGES - 1; s++) {
        if (s < KC) {
            const uint32_t aB = sbase + (uint32_t)(s * STW_A) * 4;
            const uint32_t bB = sbase + (uint32_t)(STAGES * STW_A + s * STW_B) * 4;
            const int k0 = s * 32;
            cp16(aB + dOffA0, aP + k0);  cp16(aB + dOffA1, aP + aStep + k0);
#pragma unroll
            for (int j = 0; j < BJ; j++)
                cp16(bB + dOffA0 + (uint32_t)(j * 64 * PITCH * 4), wP + j * wStep + k0);
        }
        cp_commit();
    }

    float acc[4][NT][4];
#pragma unroll
    for (int i = 0; i < 4; i++)
#pragma unroll
        for (int j = 0; j < NT; j++)
#pragma unroll
            for (int q = 0; q < 4; q++) acc[i][j][q] = 0.f;

    int bc = 0;
    int bi = STAGES - 1;

    for (int c = 0; c < KC; c++) {
        cp_wait<STAGES - 2>();
        __syncthreads();

        {
            const int cn = c + STAGES - 1;
            if (cn < KC) {
                const uint32_t aB = sbase + (uint32_t)(bi * STW_A) * 4;
                const uint32_t bB = sbase + (uint32_t)(STAGES * STW_A + bi * STW_B) * 4;
                const int k0 = cn * 32;
                cp16(aB + dOffA0, aP + k0);  cp16(aB + dOffA1, aP + aStep + k0);
#pragma unroll
                for (int j = 0; j < BJ; j++)
                    cp16(bB + dOffA0 + (uint32_t)(j * 64 * PITCH * 4), wP + j * wStep + k0);
            }
            cp_commit();
        }

        const uint32_t* sAw = (sm + bc * STW_A) + (wm + g) * PITCH + tg;
        const uint32_t* sBw = (sm + STAGES * STW_A + bc * STW_B) + (wn + g) * PITCH + tg;
#pragma unroll
        for (int ks = 0; ks < 2; ks++) {
            const int kb = ks * 8;                 // 16 halfs = 8 words per k16 step
            uint32_t af[4][4], bf[NT][2];
#pragma unroll
            for (int mt = 0; mt < 4; mt++) {
                af[mt][0] = sAw[mt * 16 * PITCH + kb];                 // (g,   2tg..2tg+1)
                af[mt][1] = sAw[mt * 16 * PITCH + 8 * PITCH + kb];     // (g+8, ...)
                af[mt][2] = sAw[mt * 16 * PITCH + kb + 4];             // (g,   2tg+8..9)
                af[mt][3] = sAw[mt * 16 * PITCH + 8 * PITCH + kb + 4];
            }
#pragma unroll
            for (int nt = 0; nt < NT; nt++) {
                bf[nt][0] = sBw[nt * 8 * PITCH + kb];
                bf[nt][1] = sBw[nt * 8 * PITCH + kb + 4];
            }
#pragma unroll
            for (int mt = 0; mt < 4; mt++)
#pragma unroll
                for (int nt = 0; nt < NT; nt++)
                    mma_f16(acc[mt][nt], af[mt], bf[nt]);
        }

        if (++bc == STAGES) bc = 0;
        if (++bi == STAGES) bi = 0;
    }

    // ---- epilogue ----
#pragma unroll
    for (int mt = 0; mt < 4; mt++) {
#pragma unroll
        for (int nt = 0; nt < NT; nt++) {
            const int row = m0 + wm + mt * 16 + g;
            const int col = n0 + wn + nt * 8 + 2 * tg;
            float v0 = acc[mt][nt][0], v1 = acc[mt][nt][1];
            float v2 = acc[mt][nt][2], v3 = acc[mt][nt][3];
            if (ACT == 1) {
                float b0 = bias[col], b1 = bias[col + 1];
                v0 += b0; v1 += b1; v2 += b0; v3 += b1;
                v0 = (v0 > 20.f) ? v0 : __logf(1.f + __expf(v0));
                v1 = (v1 > 20.f) ? v1 : __logf(1.f + __expf(v1));
                v2 = (v2 > 20.f) ? v2 : __logf(1.f + __expf(v2));
                v3 = (v3 > 20.f) ? v3 : __logf(1.f + __expf(v3));
            }
            *(float2*)(C + (size_t)row * ldc + col)       = make_float2(v0, v1);
            *(float2*)(C + (size_t)(row + 8) * ldc + col) = make_float2(v2, v3);
            if (DUAL) {
                *(__half2*)(Ch + (size_t)row * ldc + col)       = __floats2half2_rn(v0, v1);
                *(__half2*)(Ch + (size_t)(row + 8) * ldc + col) = __floats2half2_rn(v2, v3);
            }
        }
    }
}

// ---------------- causal depthwise conv (width 4) + SiLU (fp32 + fp16 out) ----------------
__global__ void conv_silu_kernel(const float* __restrict__ conv_w,
                                 const float* __restrict__ conv_b)
{
    int idx = blockIdx.x * blockDim.x + threadIdx.x;
    if (idx >= M_TOTAL * D_INNER) return;
    int d  = idx % D_INNER;
    int ml = idx / D_INNER;
    int l  = ml % SEQ_L;

    float acc = conv_b[d];
    const float* w = conv_w + d * D_CONV;
#pragma unroll
    for (int j = 0; j < D_CONV; j++) {
        int li = l - (D_CONV - 1) + j;
        if (li >= 0)
            acc = fmaf(w[j], g_xz[(size_t)(ml - (D_CONV - 1) + j) * (2 * D_INNER) + d], acc);
    }
    float v = acc / (1.f + __expf(-acc));   // silu
    g_xconv[idx]   = v;
    g_xconv_h[idx] = __float2half(v);
}

// ---------------- selective scan (+ D skip + z gating) ----------------
// 8 channels per warp, 4 lanes per channel, 4 states per lane. 512 blocks x 32.
// All arithmetic fp32 (identical to R13); y written fp16 for out_proj.
__global__ void scan_kernel(const float* __restrict__ A_log,
                            const float* __restrict__ Dp)
{
    const int gwarp = (blockIdx.x * blockDim.x + threadIdx.x) >> 5;
    const int lane  = threadIdx.x & 31;
    const int cw    = lane >> 2;
    const int q     = lane & 3;
    const int ch    = gwarp * 8 + cw;
    const int b     = ch / D_INNER;
    const int d     = ch % D_INNER;

    const float4 Alog4 = *(const float4*)(A_log + d * D_STATE + q * 4);
    const float A0 = -__expf(Alog4.x), A1 = -__expf(Alog4.y);
    const float A2 = -__expf(Alog4.z), A3 = -__expf(Alog4.w);
    const float Dv = Dp[d];

    const float* xrow  = g_xconv + (size_t)b * SEQ_L * D_INNER + d;
    const float* dtrow = g_dt    + (size_t)b * SEQ_L * D_INNER + d;
    const float* bcrow = g_xbc   + (size_t)b * SEQ_L * XBC_LD;
    const float* zrow  = g_xz    + (size_t)b * SEQ_L * (2 * D_INNER) + D_INNER + d;
    __half*      yrow  = g_y_h   + (size_t)b * SEQ_L * D_INNER + d;

    float h0 = 0.f, h1 = 0.f, h2 = 0.f, h3 = 0.f;

    float  xvA  = xrow[0],                    xvB  = xrow[D_INNER];
    float  dtA  = dtrow[0],                   dtB  = dtrow[D_INNER];
    float4 Bf4A = *(const float4*)(bcrow + DT_RANK + q * 4);
    float4 Cf4A = *(const float4*)(bcrow + DT_RANK + D_STATE + q * 4);
    float4 Bf4B = *(const float4*)(bcrow + XBC_LD + DT_RANK + q * 4);
    float4 Cf4B = *(const float4*)(bcrow + XBC_LD + DT_RANK + D_STATE + q * 4);
    float  zvA = 0.f, zvB = 0.f;
    if (q == 0) { zvA = zrow[0]; zvB = zrow[2 * D_INNER]; }

#pragma unroll 1
    for (int t = 0; t < SEQ_L; t += 2) {
        const int t2 = (t + 2 < SEQ_L) ? t + 2 : SEQ_L - 1;
        const int t3 = (t + 3 < SEQ_L) ? t + 3 : SEQ_L - 1;
        float  xv2  = xrow [(size_t)t2 * D_INNER];
        float  dt2  = dtrow[(size_t)t2 * D_INNER];
        float4 Bf42 = *(const float4*)(bcrow + t2 * XBC_LD + DT_RANK + q * 4);
        float4 Cf42 = *(const float4*)(bcrow + t2 * XBC_LD + DT_RANK + D_STATE + q * 4);
        float  xv3  = xrow [(size_t)t3 * D_INNER];
        float  dt3  = dtrow[(size_t)t3 * D_INNER];
        float4 Bf43 = *(const float4*)(bcrow + t3 * XBC_LD + DT_RANK + q * 4);
        float4 Cf43 = *(const float4*)(bcrow + t3 * XBC_LD + DT_RANK + D_STATE + q * 4);
        float  zv2 = 0.f, zv3 = 0.f;
        if (q == 0) { zv2 = zrow[(size_t)t2 * 2 * D_INNER]; zv3 = zrow[(size_t)t3 * 2 * D_INNER]; }

        // ---- step t ----
        h0 = fmaf(dtA, fmaf(A0, h0, Bf4A.x * xvA), h0);
        h1 = fmaf(dtA, fmaf(A1, h1, Bf4A.y * xvA), h1);
        h2 = fmaf(dtA, fmaf(A2, h2, Bf4A.z * xvA), h2);
        h3 = fmaf(dtA, fmaf(A3, h3, Bf4A.w * xvA), h3);
        {
            float p = fmaf(h3, Cf4A.w, fmaf(h2, Cf4A.z, fmaf(h1, Cf4A.y, h0 * Cf4A.x)));
            p += __shfl_xor_sync(0xffffffffu, p, 1);
            p += __shfl_xor_sync(0xffffffffu, p, 2);
            if (q == 0) {
                float y = fmaf(Dv, xvA, p);
                y *= zvA / (1.f + __expf(-zvA));
                yrow[(size_t)t * D_INNER] = __float2half(y);
            }
        }

        // ---- step t+1 ----
        h0 = fmaf(dtB, fmaf(A0, h0, Bf4B.x * xvB), h0);
        h1 = fmaf(dtB, fmaf(A1, h1, Bf4B.y * xvB), h1);
        h2 = fmaf(dtB, fmaf(A2, h2, Bf4B.z * xvB), h2);
        h3 = fmaf(dtB, fmaf(A3, h3, Bf4B.w * xvB), h3);
        {
            float p = fmaf(h3, Cf4B.w, fmaf(h2, Cf4B.z, fmaf(h1, Cf4B.y, h0 * Cf4B.x)));
            p += __shfl_xor_sync(0xffffffffu, p, 1);
            p += __shfl_xor_sync(0xffffffffu, p, 2);
            if (q == 0) {
                float y = fmaf(Dv, xvB, p);
                y *= zvB / (1.f + __expf(-zvB));
                yrow[(size_t)(t + 1) * D_INNER] = __float2half(y);
            }
        }

        xvA = xv2; dtA = dt2; Bf4A = Bf42; Cf4A = Cf42; zvA = zv2;
        xvB = xv3; dtB = dt3; Bf4B = Bf43; Cf4B = Cf43; zvB = zv3;
    }
}

// ---------------- launch ----------------
extern "C" void kernel_launch(void* const* d_in, const int* in_sizes, int n_in,
                              void* d_out, int out_size)
{
    const float* x          = (const float*)d_in[0];
    const float* in_proj_w  = (const float*)d_in[1];
    const float* conv_w     = (const float*)d_in[2];
    const float* conv_b     = (const float*)d_in[3];
    const float* A_log      = (const float*)d_in[4];
    const float* Dp         = (const float*)d_in[5];
    const float* dt_proj_w  = (const float*)d_in[6];
    const float* dt_proj_b  = (const float*)d_in[7];
    const float* x_proj_w   = (const float*)d_in[8];
    const float* B_proj_w   = (const float*)d_in[9];
    const float* C_proj_w   = (const float*)d_in[10];
    const float* out_proj_w = (const float*)d_in[11];
    float* out = (float*)d_out;

    // resolve scratch addresses
    float  *xz, *xbc, *dt, *wcat;
    __half *xconv_h, *xbc_h, *y_h, *wcat_h, *x_h, *win_h, *wdt_h, *wout_h;
    cudaGetSymbolAddress((void**)&xz,      g_xz);
    cudaGetSymbolAddress((void**)&xbc,     g_xbc);
    cudaGetSymbolAddress((void**)&dt,      g_dt);
    cudaGetSymbolAddress((void**)&wcat,    g_wcat);
    cudaGetSymbolAddress((void**)&xconv_h, g_xconv_h);
    cudaGetSymbolAddress((void**)&xbc_h,   g_xbc_h);
    cudaGetSymbolAddress((void**)&y_h,     g_y_h);
    cudaGetSymbolAddress((void**)&wcat_h,  g_wcat_h);
    cudaGetSymbolAddress((void**)&x_h,     g_x_h);
    cudaGetSymbolAddress((void**)&win_h,   g_win_h);
    cudaGetSymbolAddress((void**)&wdt_h,   g_wdt_h);
    cudaGetSymbolAddress((void**)&wout_h,  g_wout_h);

    cudaFuncSetAttribute(tc_gemm<256, 0, 0>, cudaFuncAttributeMaxDynamicSharedMemorySize, GCfg<256>::SMEM);
    cudaFuncSetAttribute(tc_gemm<64, 0, 1>,  cudaFuncAttributeMaxDynamicSharedMemorySize, GCfg<64>::SMEM);
    cudaFuncSetAttribute(tc_gemm<128, 1, 0>, cudaFuncAttributeMaxDynamicSharedMemorySize, GCfg<128>::SMEM);
    cudaFuncSetAttribute(tc_gemm<128, 0, 0>, cudaFuncAttributeMaxDynamicSharedMemorySize, GCfg<128>::SMEM);

    // pack [x_proj_w; B_proj_w; C_proj_w] -> g_wcat rows 0..95 (96..127 zero)
    cudaMemcpyToSymbolAsync(g_wcat, x_proj_w, (size_t)DT_RANK * D_INNER * sizeof(float),
                            0, cudaMemcpyDeviceToDevice, 0);
    cudaMemcpyToSymbolAsync(g_wcat, B_proj_w, (size_t)D_STATE * D_INNER * sizeof(float),
                            (size_t)DT_RANK * D_INNER * sizeof(float), cudaMemcpyDeviceToDevice, 0);
    cudaMemcpyToSymbolAsync(g_wcat, C_proj_w, (size_t)D_STATE * D_INNER * sizeof(float),
                            (size_t)(DT_RANK + D_STATE) * D_INNER * sizeof(float), cudaMemcpyDeviceToDevice, 0);

    // fp16 conversions of GEMM operands (~12 us total)
    {
        auto cvt = [](const float* s, __half* dptr, size_t n) {
            int n4 = (int)(n / 4);
            cvt_f16_kernel<<<(n4 + 255) / 256, 256>>>(s, dptr, n4);
        };
        cvt(x,          x_h,    (size_t)M_TOTAL * D_MODEL);
        cvt(in_proj_w,  win_h,  (size_t)2 * D_INNER * D_MODEL);
        cvt(dt_proj_w,  wdt_h,  (size_t)D_INNER * DT_RANK);
        cvt(out_proj_w, wout_h, (size_t)D_MODEL * D_INNER);
        cvt(wcat,       wcat_h, (size_t)XBC_LD * D_INNER);   // after the packing memcpys
    }

    // 1) in_proj: xz = x @ in_proj_w^T   (M=4096, N=4096, K=1024) [BN=256]
    {
        dim3 grid(2 * D_INNER / 256, M_TOTAL / 128);
        tc_gemm<256, 0, 0><<<grid, 256, GCfg<256>::SMEM>>>(
            x_h, D_MODEL, win_h, D_MODEL, nullptr, xz, nullptr, 2 * D_INNER, D_MODEL);
    }

    // 2) causal depthwise conv + silu -> g_xconv (fp32) + g_xconv_h (fp16)
    {
        int n = M_TOTAL * D_INNER;
        conv_silu_kernel<<<(n + 255) / 256, 256>>>(conv_w, conv_b);
    }

    // 3) fused x/B/C projection: xbc = xconv @ wcat^T (M=4096, N=128, K=2048) [BN=64, dual]
    {
        dim3 grid(XBC_LD / 64, M_TOTAL / 128);
        tc_gemm<64, 0, 1><<<grid, 256, GCfg<64>::SMEM>>>(
            xconv_h, D_INNER, wcat_h, D_INNER, nullptr, xbc, xbc_h, XBC_LD, D_INNER);
    }

    // 4) dt = softplus(xbc[:, :64] @ dt_proj_w^T + dt_proj_b)  (N=2048, K=64) [BN=128]
    {
        dim3 grid(D_INNER / 128, M_TOTAL / 128);
        tc_gemm<128, 1, 0><<<grid, 256, GCfg<128>::SMEM>>>(
            xbc_h, XBC_LD, wdt_h, DT_RANK, dt_proj_b, dt, nullptr, D_INNER, DT_RANK);
    }

    // 5) selective scan + D skip + silu(z) gating -> g_y_h
    scan_kernel<<<512, 32>>>(A_log, Dp);

    // 6) out = y @ out_proj_w^T   (M=4096, N=1024, K=2048) [BN=128]
    {
        dim3 grid(D_MODEL / 128, M_TOTAL / 128);
        tc_gemm<128, 0, 0><<<grid, 256, GCfg<128>::SMEM>>>(
            y_h, D_INNER, wout_h, D_INNER, nullptr, out, nullptr, D_MODEL, D_INNER);
    }
}

// round 15
// speedup vs baseline: 1.8941x; 1.3982x over previous
#include <cuda_runtime.h>
#include <cuda_fp16.h>
#include <math.h>
#include <stdint.h>

// ---------------- problem constants ----------------
#define B_SZ    2
#define SEQ_L   2048
#define D_MODEL 1024
#define D_STATE 16
#define D_CONV  4
#define D_INNER 2048
#define DT_RANK 64
#define M_TOTAL (B_SZ * SEQ_L)   // 4096 tokens
#define XBC_LD  128              // padded row stride for xbc / wcat
#define N_CH    (B_SZ * D_INNER) // 4096 scan channels
#define SC_NC   16               // scan chunks
#define SC_TC   (SEQ_L / SC_NC)  // 128 steps per chunk

// ---------------- scratch (device globals; no allocation allowed) ----------------
__device__ float  g_xz[(size_t)M_TOTAL * 2 * D_INNER];  // in_proj output (x_in | z), fp32
__device__ float  g_xconv[(size_t)M_TOTAL * D_INNER];   // conv+silu output, fp32 (scan)
__device__ __half g_xconv_h[(size_t)M_TOTAL * D_INNER]; // conv+silu output, fp16 (xbc GEMM)
__device__ float  g_xbc[(size_t)M_TOTAL * XBC_LD];      // [xdt|B|C|pad] fp32 (scan)
__device__ __half g_xbc_h[(size_t)M_TOTAL * XBC_LD];    // fp16 copy (dt GEMM A)
__device__ float  g_dt[(size_t)M_TOTAL * D_INNER];      // softplus dt, fp32 (scan)
__device__ __half g_y_h[(size_t)M_TOTAL * D_INNER];     // scan output, fp16 (out_proj A)
__device__ float  g_wcat[XBC_LD * D_INNER];             // [x_proj_w; B_proj_w; C_proj_w; 0]
__device__ __half g_wcat_h[XBC_LD * D_INNER];
__device__ __half g_x_h[(size_t)M_TOTAL * D_MODEL];
__device__ __half g_win_h[(size_t)2 * D_INNER * D_MODEL];
__device__ __half g_wdt_h[(size_t)D_INNER * DT_RANK];
__device__ __half g_wout_h[(size_t)D_MODEL * D_INNER];
// chunked-scan intermediates: layout [ch][chunk][state]
__device__ float  g_hend[(size_t)N_CH * SC_NC * D_STATE];
__device__ float  g_pprod[(size_t)N_CH * SC_NC * D_STATE];
__device__ float  g_hin[(size_t)N_CH * SC_NC * D_STATE];

// ---------------- helpers ----------------
__device__ __forceinline__ void mma_f16(float* c, const uint32_t* a, const uint32_t* b) {
    asm volatile(
        "mma.sync.aligned.m16n8k16.row.col.f32.f16.f16.f32 "
        "{%0,%1,%2,%3},{%4,%5,%6,%7},{%8,%9},{%0,%1,%2,%3};"
        : "+f"(c[0]), "+f"(c[1]), "+f"(c[2]), "+f"(c[3])
        : "r"(a[0]), "r"(a[1]), "r"(a[2]), "r"(a[3]), "r"(b[0]), "r"(b[1]));
}

__device__ __forceinline__ void cp16(uint32_t dst, const void* src) {
    asm volatile("cp.async.cg.shared.global [%0], [%1], 16;" :: "r"(dst), "l"(src));
}
__device__ __forceinline__ void cp_commit() {
    asm volatile("cp.async.commit_group;" ::: "memory");
}
template<int N>
__device__ __forceinline__ void cp_wait() {
    asm volatile("cp.async.wait_group %0;" :: "n"(N) : "memory");
}

// ---------------- fp32 -> fp16 conversion ----------------
__global__ void cvt_f16_kernel(const float* __restrict__ src, __half* __restrict__ dst, int n4)
{
    int i = blockIdx.x * blockDim.x + threadIdx.x;
    if (i >= n4) return;
    float4 v = ((const float4*)src)[i];
    ((__half2*)dst)[2 * i + 0] = __floats2half2_rn(v.x, v.y);
    ((__half2*)dst)[2 * i + 1] = __floats2half2_rn(v.z, v.w);
}

// ================= fp16 mma.sync GEMM, cp.async multistage =================
// (unchanged from R14 — BM=128, BN per shape, BK=32 halfs, warp 64x(BN/4))
#define PITCH  20

template<int BN> struct GCfg {
    static constexpr int STAGES = (BN == 256) ? 3 : 4;
    static constexpr int MINB   = (BN == 256) ? 1 : ((BN == 64) ? 3 : 2);
    static constexpr int SMEM   = STAGES * (128 + BN) * PITCH * 4;
};

template<int BN, int ACT, int DUAL>
__global__ __launch_bounds__(256, GCfg<BN>::MINB)
void tc_gemm(const __half* __restrict__ A, int lda,
             const __half* __restrict__ W, int ldw,
             const float* __restrict__ bias,
             float* __restrict__ C, __half* __restrict__ Ch, int ldc, int K)
{
    constexpr int NT     = BN / 32;
    constexpr int STAGES = GCfg<BN>::STAGES;
    constexpr int STW_A  = 128 * PITCH;
    constexpr int STW_B  = BN * PITCH;
    constexpr int BJ     = BN / 64;

    extern __shared__ uint32_t sm[];

    const int tid  = threadIdx.x;
    const int wid  = tid >> 5;
    const int lane = tid & 31;
    const int g    = lane >> 2;
    const int tg   = lane & 3;
    const int wm   = (wid & 1) * 64;
    const int wn   = (wid >> 1) * (BN / 4);
    const int m0   = blockIdx.y * 128;
    const int n0   = blockIdx.x * BN;

    const int c4 = tid & 3;
    const int r0 = tid >> 2;
    const __half* aP = A + (size_t)(m0 + r0) * lda + c4 * 8;
    const __half* wP = W + (size_t)(n0 + r0) * ldw + c4 * 8;
    const size_t aStep = (size_t)64 * lda;
    const size_t wStep = (size_t)64 * ldw;

    uint32_t sbase;
    asm("{ .reg .u64 t; cvta.to.shared.u64 t, %1; cvt.u32.u64 %0, t; }" : "=r"(sbase) : "l"(sm));
    const uint32_t dOffA0 = (uint32_t)(r0 * PITCH + c4 * 4) * 4;
    const uint32_t dOffA1 = (uint32_t)((r0 + 64) * PITCH + c4 * 4) * 4;

    const int KC = K / 32;

#pragma unroll
    for (int s = 0; s < STAGES - 1; s++) {
        if (s < KC) {
            const uint32_t aB = sbase + (uint32_t)(s * STW_A) * 4;
            const uint32_t bB = sbase + (uint32_t)(STAGES * STW_A + s * STW_B) * 4;
            const int k0 = s * 32;
            cp16(aB + dOffA0, aP + k0);  cp16(aB + dOffA1, aP + aStep + k0);
#pragma unroll
            for (int j = 0; j < BJ; j++)
                cp16(bB + dOffA0 + (uint32_t)(j * 64 * PITCH * 4), wP + j * wStep + k0);
        }
        cp_commit();
    }

    float acc[4][NT][4];
#pragma unroll
    for (int i = 0; i < 4; i++)
#pragma unroll
        for (int j = 0; j < NT; j++)
#pragma unroll
            for (int q = 0; q < 4; q++) acc[i][j][q] = 0.f;

    int bc = 0;
    int bi = STAGES - 1;

    for (int c = 0; c < KC; c++) {
        cp_wait<STAGES - 2>();
        __syncthreads();

        {
            const int cn = c + STAGES - 1;
            if (cn < KC) {
                const uint32_t aB = sbase + (uint32_t)(bi * STW_A) * 4;
                const uint32_t bB = sbase + (uint32_t)(STAGES * STW_A + bi * STW_B) * 4;
                const int k0 = cn * 32;
                cp16(aB + dOffA0, aP + k0);  cp16(aB + dOffA1, aP + aStep + k0);
#pragma unroll
                for (int j = 0; j < BJ; j++)
                    cp16(bB + dOffA0 + (uint32_t)(j * 64 * PITCH * 4), wP + j * wStep + k0);
            }
            cp_commit();
        }

        const uint32_t* sAw = (sm + bc * STW_A) + (wm + g) * PITCH + tg;
        const uint32_t* sBw = (sm + STAGES * STW_A + bc * STW_B) + (wn + g) * PITCH + tg;
#pragma unroll
        for (int ks = 0; ks < 2; ks++) {
            const int kb = ks * 8;
            uint32_t af[4][4], bf[NT][2];
#pragma unroll
            for (int mt = 0; mt < 4; mt++) {
                af[mt][0] = sAw[mt * 16 * PITCH + kb];
                af[mt][1] = sAw[mt * 16 * PITCH + 8 * PITCH + kb];
                af[mt][2] = sAw[mt * 16 * PITCH + kb + 4];
                af[mt][3] = sAw[mt * 16 * PITCH + 8 * PITCH + kb + 4];
            }
#pragma unroll
            for (int nt = 0; nt < NT; nt++) {
                bf[nt][0] = sBw[nt * 8 * PITCH + kb];
                bf[nt][1] = sBw[nt * 8 * PITCH + kb + 4];
            }
#pragma unroll
            for (int mt = 0; mt < 4; mt++)
#pragma unroll
                for (int nt = 0; nt < NT; nt++)
                    mma_f16(acc[mt][nt], af[mt], bf[nt]);
        }

        if (++bc == STAGES) bc = 0;
        if (++bi == STAGES) bi = 0;
    }

#pragma unroll
    for (int mt = 0; mt < 4; mt++) {
#pragma unroll
        for (int nt = 0; nt < NT; nt++) {
            const int row = m0 + wm + mt * 16 + g;
            const int col = n0 + wn + nt * 8 + 2 * tg;
            float v0 = acc[mt][nt][0], v1 = acc[mt][nt][1];
            float v2 = acc[mt][nt][2], v3 = acc[mt][nt][3];
            if (ACT == 1) {
                float b0 = bias[col], b1 = bias[col + 1];
                v0 += b0; v1 += b1; v2 += b0; v3 += b1;
                v0 = (v0 > 20.f) ? v0 : __logf(1.f + __expf(v0));
                v1 = (v1 > 20.f) ? v1 : __logf(1.f + __expf(v1));
                v2 = (v2 > 20.f) ? v2 : __logf(1.f + __expf(v2));
                v3 = (v3 > 20.f) ? v3 : __logf(1.f + __expf(v3));
            }
            *(float2*)(C + (size_t)row * ldc + col)       = make_float2(v0, v1);
            *(float2*)(C + (size_t)(row + 8) * ldc + col) = make_float2(v2, v3);
            if (DUAL) {
                *(__half2*)(Ch + (size_t)row * ldc + col)       = __floats2half2_rn(v0, v1);
                *(__half2*)(Ch + (size_t)(row + 8) * ldc + col) = __floats2half2_rn(v2, v3);
            }
        }
    }
}

// ---------------- causal depthwise conv (width 4) + SiLU (fp32 + fp16 out) ----------------
__global__ void conv_silu_kernel(const float* __restrict__ conv_w,
                                 const float* __restrict__ conv_b)
{
    int idx = blockIdx.x * blockDim.x + threadIdx.x;
    if (idx >= M_TOTAL * D_INNER) return;
    int d  = idx % D_INNER;
    int ml = idx / D_INNER;
    int l  = ml % SEQ_L;

    float acc = conv_b[d];
    const float* w = conv_w + d * D_CONV;
#pragma unroll
    for (int j = 0; j < D_CONV; j++) {
        int li = l - (D_CONV - 1) + j;
        if (li >= 0)
            acc = fmaf(w[j], g_xz[(size_t)(ml - (D_CONV - 1) + j) * (2 * D_INNER) + d], acc);
    }
    float v = acc / (1.f + __expf(-acc));   // silu
    g_xconv[idx]   = v;
    g_xconv_h[idx] = __float2half(v);
}

// ================= chunked parallel scan =================
// Linear recurrence: h_t = a_t*h_{t-1} + u_t,  a_t = 1 + dt*A,  u_t = dt*B_t*x_t.
// Warp layout (all passes): 8 channels/warp, 4 lanes/channel, 4 states/lane.
// 8192 warps in passes 1/3 (512 channel-groups x 16 chunks) -> ~14 warps/SMSP.

// Pass 1: per (channel, chunk): local scan from h=0, accumulate P = prod(a).
__global__ __launch_bounds__(256)
void scan_pass1(const float* __restrict__ A_log)
{
    const int gwarp = blockIdx.x * 8 + (threadIdx.x >> 5);   // 0..8191
    const int lane  = threadIdx.x & 31;
    const int chunk = gwarp & (SC_NC - 1);
    const int grp   = gwarp >> 4;         // 0..511
    const int cw    = lane >> 2;
    const int q     = lane & 3;
    const int ch    = grp * 8 + cw;
    const int b     = ch / D_INNER;
    const int d     = ch % D_INNER;

    const float4 Alog4 = *(const float4*)(A_log + d * D_STATE + q * 4);
    const float A0 = -__expf(Alog4.x), A1 = -__expf(Alog4.y);
    const float A2 = -__expf(Alog4.z), A3 = -__expf(Alog4.w);

    const int t0 = chunk * SC_TC;
    const float* xrow  = g_xconv + (size_t)(b * SEQ_L + t0) * D_INNER + d;
    const float* dtrow = g_dt    + (size_t)(b * SEQ_L + t0) * D_INNER + d;
    const float* bcrow = g_xbc   + (size_t)(b * SEQ_L + t0) * XBC_LD;

    float h0 = 0.f, h1 = 0.f, h2 = 0.f, h3 = 0.f;
    float P0 = 1.f, P1 = 1.f, P2 = 1.f, P3 = 1.f;

#pragma unroll 4
    for (int i = 0; i < SC_TC; i++) {
        float  xv  = xrow [(size_t)i * D_INNER];
        float  dtv = dtrow[(size_t)i * D_INNER];
        float4 Bf  = *(const float4*)(bcrow + i * XBC_LD + DT_RANK + q * 4);
        float  tb  = dtv * xv;
        float a0 = fmaf(dtv, A0, 1.f);  h0 = fmaf(a0, h0, tb * Bf.x);  P0 *= a0;
        float a1 = fmaf(dtv, A1, 1.f);  h1 = fmaf(a1, h1, tb * Bf.y);  P1 *= a1;
        float a2 = fmaf(dtv, A2, 1.f);  h2 = fmaf(a2, h2, tb * Bf.z);  P2 *= a2;
        float a3 = fmaf(dtv, A3, 1.f);  h3 = fmaf(a3, h3, tb * Bf.w);  P3 *= a3;
    }

    const size_t o = ((size_t)ch * SC_NC + chunk) * D_STATE + q * 4;
    *(float4*)(g_hend  + o) = make_float4(h0, h1, h2, h3);
    *(float4*)(g_pprod + o) = make_float4(P0, P1, P2, P3);
}

// Pass 2: stitch chunk summaries. One thread per (channel, state).
__global__ __launch_bounds__(256)
void scan_pass2()
{
    const int tidg = blockIdx.x * blockDim.x + threadIdx.x;   // 0..65535
    const int s  = tidg & (D_STATE - 1);
    const int ch = tidg >> 4;
    float h = 0.f;
#pragma unroll
    for (int c = 0; c < SC_NC; c++) {
        const size_t o = ((size_t)ch * SC_NC + c) * D_STATE + s;
        g_hin[o] = h;
        h = fmaf(g_pprod[o], h, g_hend[o]);
    }
}

// Pass 3: re-run each chunk from exact h_in, emit y (D skip + silu(z) gate), fp16.
__global__ __launch_bounds__(256)
void scan_pass3(const float* __restrict__ A_log, const float* __restrict__ Dp)
{
    const int gwarp = blockIdx.x * 8 + (threadIdx.x >> 5);
    const int lane  = threadIdx.x & 31;
    const int chunk = gwarp & (SC_NC - 1);
    const int grp   = gwarp >> 4;
    const int cw    = lane >> 2;
    const int q     = lane & 3;
    const int ch    = grp * 8 + cw;
    const int b     = ch / D_INNER;
    const int d     = ch % D_INNER;

    const float4 Alog4 = *(const float4*)(A_log + d * D_STATE + q * 4);
    const float A0 = -__expf(Alog4.x), A1 = -__expf(Alog4.y);
    const float A2 = -__expf(Alog4.z), A3 = -__expf(Alog4.w);
    const float Dv = Dp[d];

    const int t0 = chunk * SC_TC;
    const float* xrow  = g_xconv + (size_t)(b * SEQ_L + t0) * D_INNER + d;
    const float* dtrow = g_dt    + (size_t)(b * SEQ_L + t0) * D_INNER + d;
    const float* bcrow = g_xbc   + (size_t)(b * SEQ_L + t0) * XBC_LD;
    const float* zrow  = g_xz    + (size_t)(b * SEQ_L + t0) * (2 * D_INNER) + D_INNER + d;
    __half*      yrow  = g_y_h   + (size_t)(b * SEQ_L + t0) * D_INNER + d;

    const float4 hin = *(const float4*)(g_hin + ((size_t)ch * SC_NC + chunk) * D_STATE + q * 4);
    float h0 = hin.x, h1 = hin.y, h2 = hin.z, h3 = hin.w;

#pragma unroll 2
    for (int i = 0; i < SC_TC; i++) {
        float  xv  = xrow [(size_t)i * D_INNER];
        float  dtv = dtrow[(size_t)i * D_INNER];
        float4 Bf  = *(const float4*)(bcrow + i * XBC_LD + DT_RANK + q * 4);
        float4 Cf  = *(const float4*)(bcrow + i * XBC_LD + DT_RANK + D_STATE + q * 4);
        float  tb  = dtv * xv;
        float a0 = fmaf(dtv, A0, 1.f);  h0 = fmaf(a0, h0, tb * Bf.x);
        float a1 = fmaf(dtv, A1, 1.f);  h1 = fmaf(a1, h1, tb * Bf.y);
        float a2 = fmaf(dtv, A2, 1.f);  h2 = fmaf(a2, h2, tb * Bf.z);
        float a3 = fmaf(dtv, A3, 1.f);  h3 = fmaf(a3, h3, tb * Bf.w);

        float p = fmaf(h3, Cf.w, fmaf(h2, Cf.z, fmaf(h1, Cf.y, h0 * Cf.x)));
        p += __shfl_xor_sync(0xffffffffu, p, 1);
        p += __shfl_xor_sync(0xffffffffu, p, 2);
        if (q == 0) {
            float zv = zrow[(size_t)i * (2 * D_INNER)];
            float y  = fmaf(Dv, xv, p);
            y *= zv / (1.f + __expf(-zv));
            yrow[(size_t)i * D_INNER] = __float2half(y);
        }
    }
}

// ---------------- launch ----------------
extern "C" void kernel_launch(void* const* d_in, const int* in_sizes, int n_in,
                              void* d_out, int out_size)
{
    const float* x          = (const float*)d_in[0];
    const float* in_proj_w  = (const float*)d_in[1];
    const float* conv_w     = (const float*)d_in[2];
    const float* conv_b     = (const float*)d_in[3];
    const float* A_log      = (const float*)d_in[4];
    const float* Dp         = (const float*)d_in[5];
    const float* dt_proj_w  = (const float*)d_in[6];
    const float* dt_proj_b  = (const float*)d_in[7];
    const float* x_proj_w   = (const float*)d_in[8];
    const float* B_proj_w   = (const float*)d_in[9];
    const float* C_proj_w   = (const float*)d_in[10];
    const float* out_proj_w = (const float*)d_in[11];
    float* out = (float*)d_out;

    // resolve scratch addresses
    float  *xz, *xbc, *dt, *wcat;
    __half *xconv_h, *xbc_h, *y_h, *wcat_h, *x_h, *win_h, *wdt_h, *wout_h;
    cudaGetSymbolAddress((void**)&xz,      g_xz);
    cudaGetSymbolAddress((void**)&xbc,     g_xbc);
    cudaGetSymbolAddress((void**)&dt,      g_dt);
    cudaGetSymbolAddress((void**)&wcat,    g_wcat);
    cudaGetSymbolAddress((void**)&xconv_h, g_xconv_h);
    cudaGetSymbolAddress((void**)&xbc_h,   g_xbc_h);
    cudaGetSymbolAddress((void**)&y_h,     g_y_h);
    cudaGetSymbolAddress((void**)&wcat_h,  g_wcat_h);
    cudaGetSymbolAddress((void**)&x_h,     g_x_h);
    cudaGetSymbolAddress((void**)&win_h,   g_win_h);
    cudaGetSymbolAddress((void**)&wdt_h,   g_wdt_h);
    cudaGetSymbolAddress((void**)&wout_h,  g_wout_h);

    cudaFuncSetAttribute(tc_gemm<256, 0, 0>, cudaFuncAttributeMaxDynamicSharedMemorySize, GCfg<256>::SMEM);
    cudaFuncSetAttribute(tc_gemm<64, 0, 1>,  cudaFuncAttributeMaxDynamicSharedMemorySize, GCfg<64>::SMEM);
    cudaFuncSetAttribute(tc_gemm<128, 1, 0>, cudaFuncAttributeMaxDynamicSharedMemorySize, GCfg<128>::SMEM);
    cudaFuncSetAttribute(tc_gemm<128, 0, 0>, cudaFuncAttributeMaxDynamicSharedMemorySize, GCfg<128>::SMEM);

    // pack [x_proj_w; B_proj_w; C_proj_w] -> g_wcat rows 0..95 (96..127 zero)
    cudaMemcpyToSymbolAsync(g_wcat, x_proj_w, (size_t)DT_RANK * D_INNER * sizeof(float),
                            0, cudaMemcpyDeviceToDevice, 0);
    cudaMemcpyToSymbolAsync(g_wcat, B_proj_w, (size_t)D_STATE * D_INNER * sizeof(float),
                            (size_t)DT_RANK * D_INNER * sizeof(float), cudaMemcpyDeviceToDevice, 0);
    cudaMemcpyToSymbolAsync(g_wcat, C_proj_w, (size_t)D_STATE * D_INNER * sizeof(float),
                            (size_t)(DT_RANK + D_STATE) * D_INNER * sizeof(float), cudaMemcpyDeviceToDevice, 0);

    // fp16 conversions of GEMM operands
    {
        auto cvt = [](const float* s, __half* dptr, size_t n) {
            int n4 = (int)(n / 4);
            cvt_f16_kernel<<<(n4 + 255) / 256, 256>>>(s, dptr, n4);
        };
        cvt(x,          x_h,    (size_t)M_TOTAL * D_MODEL);
        cvt(in_proj_w,  win_h,  (size_t)2 * D_INNER * D_MODEL);
        cvt(dt_proj_w,  wdt_h,  (size_t)D_INNER * DT_RANK);
        cvt(out_proj_w, wout_h, (size_t)D_MODEL * D_INNER);
        cvt(wcat,       wcat_h, (size_t)XBC_LD * D_INNER);
    }

    // 1) in_proj: xz = x @ in_proj_w^T   (M=4096, N=4096, K=1024) [BN=256]
    {
        dim3 grid(2 * D_INNER / 256, M_TOTAL / 128);
        tc_gemm<256, 0, 0><<<grid, 256, GCfg<256>::SMEM>>>(
            x_h, D_MODEL, win_h, D_MODEL, nullptr, xz, nullptr, 2 * D_INNER, D_MODEL);
    }

    // 2) causal depthwise conv + silu -> g_xconv (fp32) + g_xconv_h (fp16)
    {
        int n = M_TOTAL * D_INNER;
        conv_silu_kernel<<<(n + 255) / 256, 256>>>(conv_w, conv_b);
    }

    // 3) fused x/B/C projection: xbc = xconv @ wcat^T (M=4096, N=128, K=2048) [BN=64, dual]
    {
        dim3 grid(XBC_LD / 64, M_TOTAL / 128);
        tc_gemm<64, 0, 1><<<grid, 256, GCfg<64>::SMEM>>>(
            xconv_h, D_INNER, wcat_h, D_INNER, nullptr, xbc, xbc_h, XBC_LD, D_INNER);
    }

    // 4) dt = softplus(xbc[:, :64] @ dt_proj_w^T + dt_proj_b)  (N=2048, K=64) [BN=128]
    {
        dim3 grid(D_INNER / 128, M_TOTAL / 128);
        tc_gemm<128, 1, 0><<<grid, 256, GCfg<128>::SMEM>>>(
            xbc_h, XBC_LD, wdt_h, DT_RANK, dt_proj_b, dt, nullptr, D_INNER, DT_RANK);
    }

    // 5) chunked parallel scan: 8192 warps in passes 1/3
    scan_pass1<<<1024, 256>>>(A_log);
    scan_pass2<<<256, 256>>>();
    scan_pass3<<<1024, 256>>>(A_log, Dp);

    // 6) out = y @ out_proj_w^T   (M=4096, N=1024, K=2048) [BN=128]
    {
        dim3 grid(D_MODEL / 128, M_TOTAL / 128);
        tc_gemm<128, 0, 0><<<grid, 256, GCfg<128>::SMEM>>>(
            y_h, D_INNER, wout_h, D_INNER, nullptr, out, nullptr, D_MODEL, D_INNER);
    }
}

// round 16
// speedup vs baseline: 1.9417x; 1.0251x over previous
#include <cuda_runtime.h>
#include <cuda_fp16.h>
#include <math.h>
#include <stdint.h>

// ---------------- problem constants ----------------
#define B_SZ    2
#define SEQ_L   2048
#define D_MODEL 1024
#define D_STATE 16
#define D_CONV  4
#define D_INNER 2048
#define DT_RANK 64
#define M_TOTAL (B_SZ * SEQ_L)   // 4096 tokens
#define XBC_LD  128              // padded row stride for xbc / wcat
#define N_CH    (B_SZ * D_INNER) // 4096 scan channels
#define SC_NC   16               // scan chunks
#define SC_TC   (SEQ_L / SC_NC)  // 128 steps per chunk

// ---------------- scratch (device globals; no allocation allowed) ----------------
__device__ float  g_xz[(size_t)M_TOTAL * 2 * D_INNER];  // in_proj output (x_in | z), fp32
__device__ float  g_xconv[(size_t)M_TOTAL * D_INNER];   // conv+silu output, fp32 (scan)
__device__ __half g_xconv_h[(size_t)M_TOTAL * D_INNER]; // conv+silu output, fp16 (xbc GEMM)
__device__ float  g_xbc[(size_t)M_TOTAL * XBC_LD];      // [xdt|B|C|pad] fp32 (scan)
__device__ __half g_xbc_h[(size_t)M_TOTAL * XBC_LD];    // fp16 copy (dt GEMM A)
__device__ float  g_dt[(size_t)M_TOTAL * D_INNER];      // softplus dt, fp32 (scan)
__device__ __half g_y_h[(size_t)M_TOTAL * D_INNER];     // scan output, fp16 (out_proj A)
__device__ float  g_wcat[XBC_LD * D_INNER];             // [x_proj_w; B_proj_w; C_proj_w; 0]
__device__ __half g_wcat_h[XBC_LD * D_INNER];
__device__ __half g_x_h[(size_t)M_TOTAL * D_MODEL];
__device__ __half g_win_h[(size_t)2 * D_INNER * D_MODEL];
__device__ __half g_wdt_h[(size_t)D_INNER * DT_RANK];
__device__ __half g_wout_h[(size_t)D_MODEL * D_INNER];
// chunked-scan intermediates: layout [ch][chunk][state]
__device__ float  g_hend[(size_t)N_CH * SC_NC * D_STATE];
__device__ float  g_pprod[(size_t)N_CH * SC_NC * D_STATE];
__device__ float  g_hin[(size_t)N_CH * SC_NC * D_STATE];

// ---------------- helpers ----------------
__device__ __forceinline__ void mma_f16(float* c, const uint32_t* a, const uint32_t* b) {
    asm volatile(
        "mma.sync.aligned.m16n8k16.row.col.f32.f16.f16.f32 "
        "{%0,%1,%2,%3},{%4,%5,%6,%7},{%8,%9},{%0,%1,%2,%3};"
        : "+f"(c[0]), "+f"(c[1]), "+f"(c[2]), "+f"(c[3])
        : "r"(a[0]), "r"(a[1]), "r"(a[2]), "r"(a[3]), "r"(b[0]), "r"(b[1]));
}

#define LDSM_X4(r0, r1, r2, r3, addr) \
    asm volatile("ldmatrix.sync.aligned.m8n8.x4.shared.b16 {%0,%1,%2,%3}, [%4];" \
                 : "=r"(r0), "=r"(r1), "=r"(r2), "=r"(r3) : "r"(addr))
#define LDSM_X2(r0, r1, addr) \
    asm volatile("ldmatrix.sync.aligned.m8n8.x2.shared.b16 {%0,%1}, [%2];" \
                 : "=r"(r0), "=r"(r1) : "r"(addr))

__device__ __forceinline__ void cp16(uint32_t dst, const void* src) {
    asm volatile("cp.async.cg.shared.global [%0], [%1], 16;" :: "r"(dst), "l"(src));
}
__device__ __forceinline__ void cp_commit() {
    asm volatile("cp.async.commit_group;" ::: "memory");
}
template<int N>
__device__ __forceinline__ void cp_wait() {
    asm volatile("cp.async.wait_group %0;" :: "n"(N) : "memory");
}

// ---------------- fp32 -> fp16 conversion ----------------
__global__ void cvt_f16_kernel(const float* __restrict__ src, __half* __restrict__ dst, int n4)
{
    int i = blockIdx.x * blockDim.x + threadIdx.x;
    if (i >= n4) return;
    float4 v = ((const float4*)src)[i];
    ((__half2*)dst)[2 * i + 0] = __floats2half2_rn(v.x, v.y);
    ((__half2*)dst)[2 * i + 1] = __floats2half2_rn(v.z, v.w);
}

// ================= fp16 mma.sync GEMM, cp.async multistage, ldmatrix =================
// C[m,n] = act( sum_k A[m,k] * W[n,k] (+ bias[n]) ), A/W fp16, accum fp32.
// BM in {128,256} (BN = BM/2), BK = 32 halfs. THREADS = 2*BM.
// Warps: WARPS_M = BM/64 along m, 4 along n. Warp tile 64 x (BN/4).
// smem m-major, row = 16 words + 4 pad (PITCH 20). Fragments via ldmatrix:
// 8 rows x 16B per wavefront, stride-20 rows cover all 32 banks (verified).
// ACT: 1 = softplus(v + bias[n]).  DUAL: also write fp16 copy to Ch.
#define PITCH  20

template<int BM> struct GCfg {
    static constexpr int BN     = BM / 2;
    static constexpr int STAGES = (BM == 256) ? 3 : 4;
    static constexpr int MINB   = (BM == 256) ? 1 : 3;
    static constexpr int SMEM   = STAGES * (BM + BN) * PITCH * 4;
};

template<int BM, int ACT, int DUAL>
__global__ __launch_bounds__(BM * 2, GCfg<BM>::MINB)
void tc_gemm(const __half* __restrict__ A, int lda,
             const __half* __restrict__ W, int ldw,
             const float* __restrict__ bias,
             float* __restrict__ C, __half* __restrict__ Ch, int ldc, int K)
{
    constexpr int BN      = BM / 2;
    constexpr int WARPS_M = BM / 64;
    constexpr int NT      = BN / 32;       // n8 tiles per warp (warp n-extent = NT*8)
    constexpr int STAGES  = GCfg<BM>::STAGES;
    constexpr int STW_A   = BM * PITCH;    // words
    constexpr int STW_B   = BN * PITCH;

    extern __shared__ uint32_t sm[];

    const int tid  = threadIdx.x;
    const int wid  = tid >> 5;
    const int lane = tid & 31;
    const int g    = lane >> 2;
    const int tg   = lane & 3;
    const int wm   = (wid % WARPS_M) * 64;
    const int wn   = (wid / WARPS_M) * (NT * 8);
    const int m0   = blockIdx.y * BM;
    const int n0   = blockIdx.x * BN;

    // loader: A rows {r0, r0+BM/2}; B row r0 (BM/2 == BN); 16B slot c4
    const int c4 = tid & 3;
    const int r0 = tid >> 2;               // 0..BM/2-1
    const __half* aP = A + (size_t)(m0 + r0) * lda + c4 * 8;
    const __half* wP = W + (size_t)(n0 + r0) * ldw + c4 * 8;
    const size_t aStep = (size_t)(BM / 2) * lda;

    uint32_t sbase;
    asm("{ .reg .u64 t; cvta.to.shared.u64 t, %1; cvt.u32.u64 %0, t; }" : "=r"(sbase) : "l"(sm));
    const uint32_t dOffA0 = (uint32_t)(r0 * PITCH + c4 * 4) * 4;           // bytes
    const uint32_t dOffA1 = (uint32_t)((r0 + BM / 2) * PITCH + c4 * 4) * 4;
    const uint32_t dOffB  = dOffA0;

    // ldmatrix per-lane address components (bytes, within a tile)
    const uint32_t aLdm = (uint32_t)(((wm + (lane & 15)) * PITCH + ((lane >> 4) << 2)) * 4);
    const uint32_t bLdm = (uint32_t)(((wn + (lane & 7)) * PITCH + (((lane >> 3) & 1) << 2)) * 4);

    const int KC = K / 32;

    // prologue
#pragma unroll
    for (int s = 0; s < STAGES - 1; s++) {
        if (s < KC) {
            const uint32_t aB = sbase + (uint32_t)(s * STW_A) * 4;
            const uint32_t bB = sbase + (uint32_t)(STAGES * STW_A + s * STW_B) * 4;
            const int k0 = s * 32;
            cp16(aB + dOffA0, aP + k0);  cp16(aB + dOffA1, aP + aStep + k0);
            cp16(bB + dOffB, wP + k0);
        }
        cp_commit();
    }

    float acc[4][NT][4];
#pragma unroll
    for (int i = 0; i < 4; i++)
#pragma unroll
        for (int j = 0; j < NT; j++)
#pragma unroll
            for (int q = 0; q < 4; q++) acc[i][j][q] = 0.f;

    int bc = 0;
    int bi = STAGES - 1;

    for (int c = 0; c < KC; c++) {
        cp_wait<STAGES - 2>();
        __syncthreads();

        {
            const int cn = c + STAGES - 1;
            if (cn < KC) {
                const uint32_t aB = sbase + (uint32_t)(bi * STW_A) * 4;
                const uint32_t bB = sbase + (uint32_t)(STAGES * STW_A + bi * STW_B) * 4;
                const int k0 = cn * 32;
                cp16(aB + dOffA0, aP + k0);  cp16(aB + dOffA1, aP + aStep + k0);
                cp16(bB + dOffB, wP + k0);
            }
            cp_commit();
        }

        const uint32_t sA = sbase + (uint32_t)(bc * STW_A) * 4;
        const uint32_t sB = sbase + (uint32_t)(STAGES * STW_A + bc * STW_B) * 4;
#pragma unroll
        for (int ks = 0; ks < 2; ks++) {
            const uint32_t kbB = (uint32_t)(ks * 8 * 4);   // 8 words in bytes
            uint32_t af[4][4], bf[NT][2];
#pragma unroll
            for (int mt = 0; mt < 4; mt++)
                LDSM_X4(af[mt][0], af[mt][1], af[mt][2], af[mt][3],
                        sA + aLdm + (uint32_t)(mt * 16 * PITCH * 4) + kbB);
#pragma unroll
            for (int nt = 0; nt < NT; nt++)
                LDSM_X2(bf[nt][0], bf[nt][1],
                        sB + bLdm + (uint32_t)(nt * 8 * PITCH * 4) + kbB);
#pragma unroll
            for (int mt = 0; mt < 4; mt++)
#pragma unroll
                for (int nt = 0; nt < NT; nt++)
                    mma_f16(acc[mt][nt], af[mt], bf[nt]);
        }

        if (++bc == STAGES) bc = 0;
        if (++bi == STAGES) bi = 0;
    }

    // ---- epilogue ----
#pragma unroll
    for (int mt = 0; mt < 4; mt++) {
#pragma unroll
        for (int nt = 0; nt < NT; nt++) {
            const int row = m0 + wm + mt * 16 + g;
            const int col = n0 + wn + nt * 8 + 2 * tg;
            float v0 = acc[mt][nt][0], v1 = acc[mt][nt][1];
            float v2 = acc[mt][nt][2], v3 = acc[mt][nt][3];
            if (ACT == 1) {
                float b0 = bias[col], b1 = bias[col + 1];
                v0 += b0; v1 += b1; v2 += b0; v3 += b1;
                v0 = (v0 > 20.f) ? v0 : __logf(1.f + __expf(v0));
                v1 = (v1 > 20.f) ? v1 : __logf(1.f + __expf(v1));
                v2 = (v2 > 20.f) ? v2 : __logf(1.f + __expf(v2));
                v3 = (v3 > 20.f) ? v3 : __logf(1.f + __expf(v3));
            }
            *(float2*)(C + (size_t)row * ldc + col)       = make_float2(v0, v1);
            *(float2*)(C + (size_t)(row + 8) * ldc + col) = make_float2(v2, v3);
            if (DUAL) {
                *(__half2*)(Ch + (size_t)row * ldc + col)       = __floats2half2_rn(v0, v1);
                *(__half2*)(Ch + (size_t)(row + 8) * ldc + col) = __floats2half2_rn(v2, v3);
            }
        }
    }
}

// ---------------- causal depthwise conv (width 4) + SiLU (fp32 + fp16 out) ----------------
__global__ void conv_silu_kernel(const float* __restrict__ conv_w,
                                 const float* __restrict__ conv_b)
{
    int idx = blockIdx.x * blockDim.x + threadIdx.x;
    if (idx >= M_TOTAL * D_INNER) return;
    int d  = idx % D_INNER;
    int ml = idx / D_INNER;
    int l  = ml % SEQ_L;

    float acc = conv_b[d];
    const float* w = conv_w + d * D_CONV;
#pragma unroll
    for (int j = 0; j < D_CONV; j++) {
        int li = l - (D_CONV - 1) + j;
        if (li >= 0)
            acc = fmaf(w[j], g_xz[(size_t)(ml - (D_CONV - 1) + j) * (2 * D_INNER) + d], acc);
    }
    float v = acc / (1.f + __expf(-acc));   // silu
    g_xconv[idx]   = v;
    g_xconv_h[idx] = __float2half(v);
}

// ================= chunked parallel scan (unchanged from R15) =================
__global__ __launch_bounds__(256)
void scan_pass1(const float* __restrict__ A_log)
{
    const int gwarp = blockIdx.x * 8 + (threadIdx.x >> 5);
    const int lane  = threadIdx.x & 31;
    const int chunk = gwarp & (SC_NC - 1);
    const int grp   = gwarp >> 4;
    const int cw    = lane >> 2;
    const int q     = lane & 3;
    const int ch    = grp * 8 + cw;
    const int b     = ch / D_INNER;
    const int d     = ch % D_INNER;

    const float4 Alog4 = *(const float4*)(A_log + d * D_STATE + q * 4);
    const float A0 = -__expf(Alog4.x), A1 = -__expf(Alog4.y);
    const float A2 = -__expf(Alog4.z), A3 = -__expf(Alog4.w);

    const int t0 = chunk * SC_TC;
    const float* xrow  = g_xconv + (size_t)(b * SEQ_L + t0) * D_INNER + d;
    const float* dtrow = g_dt    + (size_t)(b * SEQ_L + t0) * D_INNER + d;
    const float* bcrow = g_xbc   + (size_t)(b * SEQ_L + t0) * XBC_LD;

    float h0 = 0.f, h1 = 0.f, h2 = 0.f, h3 = 0.f;
    float P0 = 1.f, P1 = 1.f, P2 = 1.f, P3 = 1.f;

#pragma unroll 4
    for (int i = 0; i < SC_TC; i++) {
        float  xv  = xrow [(size_t)i * D_INNER];
        float  dtv = dtrow[(size_t)i * D_INNER];
        float4 Bf  = *(const float4*)(bcrow + i * XBC_LD + DT_RANK + q * 4);
        float  tb  = dtv * xv;
        float a0 = fmaf(dtv, A0, 1.f);  h0 = fmaf(a0, h0, tb * Bf.x);  P0 *= a0;
        float a1 = fmaf(dtv, A1, 1.f);  h1 = fmaf(a1, h1, tb * Bf.y);  P1 *= a1;
        float a2 = fmaf(dtv, A2, 1.f);  h2 = fmaf(a2, h2, tb * Bf.z);  P2 *= a2;
        float a3 = fmaf(dtv, A3, 1.f);  h3 = fmaf(a3, h3, tb * Bf.w);  P3 *= a3;
    }

    const size_t o = ((size_t)ch * SC_NC + chunk) * D_STATE + q * 4;
    *(float4*)(g_hend  + o) = make_float4(h0, h1, h2, h3);
    *(float4*)(g_pprod + o) = make_float4(P0, P1, P2, P3);
}

__global__ __launch_bounds__(256)
void scan_pass2()
{
    const int tidg = blockIdx.x * blockDim.x + threadIdx.x;
    const int s  = tidg & (D_STATE - 1);
    const int ch = tidg >> 4;
    float h = 0.f;
#pragma unroll
    for (int c = 0; c < SC_NC; c++) {
        const size_t o = ((size_t)ch * SC_NC + c) * D_STATE + s;
        g_hin[o] = h;
        h = fmaf(g_pprod[o], h, g_hend[o]);
    }
}

__global__ __launch_bounds__(256)
void scan_pass3(const float* __restrict__ A_log, const float* __restrict__ Dp)
{
    const int gwarp = blockIdx.x * 8 + (threadIdx.x >> 5);
    const int lane  = threadIdx.x & 31;
    const int chunk = gwarp & (SC_NC - 1);
    const int grp   = gwarp >> 4;
    const int cw    = lane >> 2;
    const int q     = lane & 3;
    const int ch    = grp * 8 + cw;
    const int b     = ch / D_INNER;
    const int d     = ch % D_INNER;

    const float4 Alog4 = *(const float4*)(A_log + d * D_STATE + q * 4);
    const float A0 = -__expf(Alog4.x), A1 = -__expf(Alog4.y);
    const float A2 = -__expf(Alog4.z), A3 = -__expf(Alog4.w);
    const float Dv = Dp[d];

    const int t0 = chunk * SC_TC;
    const float* xrow  = g_xconv + (size_t)(b * SEQ_L + t0) * D_INNER + d;
    const float* dtrow = g_dt    + (size_t)(b * SEQ_L + t0) * D_INNER + d;
    const float* bcrow = g_xbc   + (size_t)(b * SEQ_L + t0) * XBC_LD;
    const float* zrow  = g_xz    + (size_t)(b * SEQ_L + t0) * (2 * D_INNER) + D_INNER + d;
    __half*      yrow  = g_y_h   + (size_t)(b * SEQ_L + t0) * D_INNER + d;

    const float4 hin = *(const float4*)(g_hin + ((size_t)ch * SC_NC + chunk) * D_STATE + q * 4);
    float h0 = hin.x, h1 = hin.y, h2 = hin.z, h3 = hin.w;

#pragma unroll 2
    for (int i = 0; i < SC_TC; i++) {
        float  xv  = xrow [(size_t)i * D_INNER];
        float  dtv = dtrow[(size_t)i * D_INNER];
        float4 Bf  = *(const float4*)(bcrow + i * XBC_LD + DT_RANK + q * 4);
        float4 Cf  = *(const float4*)(bcrow + i * XBC_LD + DT_RANK + D_STATE + q * 4);
        float  tb  = dtv * xv;
        float a0 = fmaf(dtv, A0, 1.f);  h0 = fmaf(a0, h0, tb * Bf.x);
        float a1 = fmaf(dtv, A1, 1.f);  h1 = fmaf(a1, h1, tb * Bf.y);
        float a2 = fmaf(dtv, A2, 1.f);  h2 = fmaf(a2, h2, tb * Bf.z);
        float a3 = fmaf(dtv, A3, 1.f);  h3 = fmaf(a3, h3, tb * Bf.w);

        float p = fmaf(h3, Cf.w, fmaf(h2, Cf.z, fmaf(h1, Cf.y, h0 * Cf.x)));
        p += __shfl_xor_sync(0xffffffffu, p, 1);
        p += __shfl_xor_sync(0xffffffffu, p, 2);
        if (q == 0) {
            float zv = zrow[(size_t)i * (2 * D_INNER)];
            float y  = fmaf(Dv, xv, p);
            y *= zv / (1.f + __expf(-zv));
            yrow[(size_t)i * D_INNER] = __float2half(y);
        }
    }
}

// ---------------- launch ----------------
extern "C" void kernel_launch(void* const* d_in, const int* in_sizes, int n_in,
                              void* d_out, int out_size)
{
    const float* x          = (const float*)d_in[0];
    const float* in_proj_w  = (const float*)d_in[1];
    const float* conv_w     = (const float*)d_in[2];
    const float* conv_b     = (const float*)d_in[3];
    const float* A_log      = (const float*)d_in[4];
    const float* Dp         = (const float*)d_in[5];
    const float* dt_proj_w  = (const float*)d_in[6];
    const float* dt_proj_b  = (const float*)d_in[7];
    const float* x_proj_w   = (const float*)d_in[8];
    const float* B_proj_w   = (const float*)d_in[9];
    const float* C_proj_w   = (const float*)d_in[10];
    const float* out_proj_w = (const float*)d_in[11];
    float* out = (float*)d_out;

    // resolve scratch addresses
    float  *xz, *xbc, *dt, *wcat;
    __half *xconv_h, *xbc_h, *y_h, *wcat_h, *x_h, *win_h, *wdt_h, *wout_h;
    cudaGetSymbolAddress((void**)&xz,      g_xz);
    cudaGetSymbolAddress((void**)&xbc,     g_xbc);
    cudaGetSymbolAddress((void**)&dt,      g_dt);
    cudaGetSymbolAddress((void**)&wcat,    g_wcat);
    cudaGetSymbolAddress((void**)&xconv_h, g_xconv_h);
    cudaGetSymbolAddress((void**)&xbc_h,   g_xbc_h);
    cudaGetSymbolAddress((void**)&y_h,     g_y_h);
    cudaGetSymbolAddress((void**)&wcat_h,  g_wcat_h);
    cudaGetSymbolAddress((void**)&x_h,     g_x_h);
    cudaGetSymbolAddress((void**)&win_h,   g_win_h);
    cudaGetSymbolAddress((void**)&wdt_h,   g_wdt_h);
    cudaGetSymbolAddress((void**)&wout_h,  g_wout_h);

    cudaFuncSetAttribute(tc_gemm<256, 0, 0>, cudaFuncAttributeMaxDynamicSharedMemorySize, GCfg<256>::SMEM);
    cudaFuncSetAttribute(tc_gemm<256, 1, 0>, cudaFuncAttributeMaxDynamicSharedMemorySize, GCfg<256>::SMEM);
    cudaFuncSetAttribute(tc_gemm<128, 0, 1>, cudaFuncAttributeMaxDynamicSharedMemorySize, GCfg<128>::SMEM);

    // pack [x_proj_w; B_proj_w; C_proj_w] -> g_wcat rows 0..95 (96..127 zero)
    cudaMemcpyToSymbolAsync(g_wcat, x_proj_w, (size_t)DT_RANK * D_INNER * sizeof(float),
                            0, cudaMemcpyDeviceToDevice, 0);
    cudaMemcpyToSymbolAsync(g_wcat, B_proj_w, (size_t)D_STATE * D_INNER * sizeof(float),
                            (size_t)DT_RANK * D_INNER * sizeof(float), cudaMemcpyDeviceToDevice, 0);
    cudaMemcpyToSymbolAsync(g_wcat, C_proj_w, (size_t)D_STATE * D_INNER * sizeof(float),
                            (size_t)(DT_RANK + D_STATE) * D_INNER * sizeof(float), cudaMemcpyDeviceToDevice, 0);

    // fp16 conversions of GEMM operands
    {
        auto cvt = [](const float* s, __half* dptr, size_t n) {
            int n4 = (int)(n / 4);
            cvt_f16_kernel<<<(n4 + 255) / 256, 256>>>(s, dptr, n4);
        };
        cvt(x,          x_h,    (size_t)M_TOTAL * D_MODEL);
        cvt(in_proj_w,  win_h,  (size_t)2 * D_INNER * D_MODEL);
        cvt(dt_proj_w,  wdt_h,  (size_t)D_INNER * DT_RANK);
        cvt(out_proj_w, wout_h, (size_t)D_MODEL * D_INNER);
        cvt(wcat,       wcat_h, (size_t)XBC_LD * D_INNER);
    }

    // 1) in_proj: xz = x @ in_proj_w^T   (M=4096, N=4096, K=1024) [BM=256, BN=128]
    {
        dim3 grid(2 * D_INNER / 128, M_TOTAL / 256);
        tc_gemm<256, 0, 0><<<grid, 512, GCfg<256>::SMEM>>>(
            x_h, D_MODEL, win_h, D_MODEL, nullptr, xz, nullptr, 2 * D_INNER, D_MODEL);
    }

    // 2) causal depthwise conv + silu -> g_xconv (fp32) + g_xconv_h (fp16)
    {
        int n = M_TOTAL * D_INNER;
        conv_silu_kernel<<<(n + 255) / 256, 256>>>(conv_w, conv_b);
    }

    // 3) fused x/B/C projection: xbc = xconv @ wcat^T (M=4096, N=128, K=2048) [BM=128, BN=64, dual]
    {
        dim3 grid(XBC_LD / 64, M_TOTAL / 128);
        tc_gemm<128, 0, 1><<<grid, 256, GCfg<128>::SMEM>>>(
            xconv_h, D_INNER, wcat_h, D_INNER, nullptr, xbc, xbc_h, XBC_LD, D_INNER);
    }

    // 4) dt = softplus(xbc[:, :64] @ dt_proj_w^T + dt_proj_b)  (N=2048, K=64) [BM=256, BN=128]
    {
        dim3 grid(D_INNER / 128, M_TOTAL / 256);
        tc_gemm<256, 1, 0><<<grid, 512, GCfg<256>::SMEM>>>(
            xbc_h, XBC_LD, wdt_h, DT_RANK, dt_proj_b, dt, nullptr, D_INNER, DT_RANK);
    }

    // 5) chunked parallel scan
    scan_pass1<<<1024, 256>>>(A_log);
    scan_pass2<<<256, 256>>>();
    scan_pass3<<<1024, 256>>>(A_log, Dp);

    // 6) out = y @ out_proj_w^T   (M=4096, N=1024, K=2048) [BM=256, BN=128]
    {
        dim3 grid(D_MODEL / 128, M_TOTAL / 256);
        tc_gemm<256, 0, 0><<<grid, 512, GCfg<256>::SMEM>>>(
            y_h, D_INNER, wout_h, D_INNER, nullptr, out, nullptr, D_MODEL, D_INNER);
    }
}

// round 17
// speedup vs baseline: 1.9961x; 1.0280x over previous
#include <cuda_runtime.h>
#include <cuda_fp16.h>
#include <math.h>
#include <stdint.h>

// ---------------- problem constants ----------------
#define B_SZ    2
#define SEQ_L   2048
#define D_MODEL 1024
#define D_STATE 16
#define D_CONV  4
#define D_INNER 2048
#define DT_RANK 64
#define M_TOTAL (B_SZ * SEQ_L)   // 4096 tokens
#define XBC_LD  128              // padded row stride for xbc / wcat
#define N_CH    (B_SZ * D_INNER) // 4096 scan channels
#define SC_NC   16               // scan chunks
#define SC_TC   (SEQ_L / SC_NC)  // 128 steps per chunk

// ---------------- scratch (device globals; no allocation allowed) ----------------
__device__ float  g_xz[(size_t)M_TOTAL * 2 * D_INNER];  // in_proj output (x_in | z), fp32
__device__ float  g_xconv[(size_t)M_TOTAL * D_INNER];   // conv+silu output, fp32 (scan)
__device__ __half g_xconv_h[(size_t)M_TOTAL * D_INNER]; // conv+silu output, fp16 (xbc GEMM)
__device__ float  g_xbc[(size_t)M_TOTAL * XBC_LD];      // [xdt|B|C|pad] fp32 (scan)
__device__ __half g_xbc_h[(size_t)M_TOTAL * XBC_LD];    // fp16 copy (dt GEMM A)
__device__ float  g_dt[(size_t)M_TOTAL * D_INNER];      // softplus dt, fp32 (scan)
__device__ __half g_y_h[(size_t)M_TOTAL * D_INNER];     // scan output, fp16 (out_proj A)
__device__ float  g_wcat[XBC_LD * D_INNER];             // [x_proj_w; B_proj_w; C_proj_w; 0]
__device__ __half g_wcat_h[XBC_LD * D_INNER];
__device__ __half g_x_h[(size_t)M_TOTAL * D_MODEL];
__device__ __half g_win_h[(size_t)2 * D_INNER * D_MODEL];
__device__ __half g_wdt_h[(size_t)D_INNER * DT_RANK];
__device__ __half g_wout_h[(size_t)D_MODEL * D_INNER];
// chunked-scan intermediates: layout [ch][chunk][state]
__device__ float  g_hend[(size_t)N_CH * SC_NC * D_STATE];
__device__ float  g_pprod[(size_t)N_CH * SC_NC * D_STATE];
__device__ float  g_hin[(size_t)N_CH * SC_NC * D_STATE];

// ---------------- helpers ----------------
__device__ __forceinline__ void mma_f16(float* c, const uint32_t* a, const uint32_t* b) {
    asm volatile(
        "mma.sync.aligned.m16n8k16.row.col.f32.f16.f16.f32 "
        "{%0,%1,%2,%3},{%4,%5,%6,%7},{%8,%9},{%0,%1,%2,%3};"
        : "+f"(c[0]), "+f"(c[1]), "+f"(c[2]), "+f"(c[3])
        : "r"(a[0]), "r"(a[1]), "r"(a[2]), "r"(a[3]), "r"(b[0]), "r"(b[1]));
}

#define LDSM_X4(r0, r1, r2, r3, addr) \
    asm volatile("ldmatrix.sync.aligned.m8n8.x4.shared.b16 {%0,%1,%2,%3}, [%4];" \
                 : "=r"(r0), "=r"(r1), "=r"(r2), "=r"(r3) : "r"(addr))

__device__ __forceinline__ void cp16(uint32_t dst, const void* src) {
    asm volatile("cp.async.cg.shared.global [%0], [%1], 16;" :: "r"(dst), "l"(src));
}
__device__ __forceinline__ void cp_commit() {
    asm volatile("cp.async.commit_group;" ::: "memory");
}
template<int N>
__device__ __forceinline__ void cp_wait() {
    asm volatile("cp.async.wait_group %0;" :: "n"(N) : "memory");
}

// ---------------- fp32 -> fp16 conversion ----------------
__global__ void cvt_f16_kernel(const float* __restrict__ src, __half* __restrict__ dst, int n4)
{
    int i = blockIdx.x * blockDim.x + threadIdx.x;
    if (i >= n4) return;
    float4 v = ((const float4*)src)[i];
    ((__half2*)dst)[2 * i + 0] = __floats2half2_rn(v.x, v.y);
    ((__half2*)dst)[2 * i + 1] = __floats2half2_rn(v.z, v.w);
}

// ================= fp16 mma.sync GEMM, cp.async multistage, ldmatrix =================
// C[m,n] = act( sum_k A[m,k] * W[n,k] (+ bias[n]) ), A/W fp16, accum fp32.
// BM in {128,256} (BN = BM/2), BK = 32 halfs. THREADS = 2*BM.
// Warps: WARPS_M = BM/64 along m, 4 along n. Warp tile 64 x (BN/4).
// smem m-major, row = 16 words + 4 pad (PITCH 20).
// Per chunk: ALL fragment ldmatrix issued back-to-back (latency batched),
// B fragments fetched two n8-tiles per ldmatrix.x4, then all MMAs.
// ACT: 1 = softplus(v + bias[n]).  DUAL: also write fp16 copy to Ch.
#define PITCH  20

template<int BM> struct GCfg {
    static constexpr int BN     = BM / 2;
    static constexpr int STAGES = 4;
    static constexpr int MINB   = (BM == 256) ? 1 : 2;
    static constexpr int SMEM   = STAGES * (BM + BN) * PITCH * 4;
};

template<int BM, int ACT, int DUAL>
__global__ __launch_bounds__(BM * 2, GCfg<BM>::MINB)
void tc_gemm(const __half* __restrict__ A, int lda,
             const __half* __restrict__ W, int ldw,
             const float* __restrict__ bias,
             float* __restrict__ C, __half* __restrict__ Ch, int ldc, int K)
{
    constexpr int BN      = BM / 2;
    constexpr int WARPS_M = BM / 64;
    constexpr int NT      = BN / 32;       // n8 tiles per warp (even)
    constexpr int NP      = NT / 2;        // B ldsm.x4 pairs
    constexpr int STAGES  = GCfg<BM>::STAGES;
    constexpr int STW_A   = BM * PITCH;    // words
    constexpr int STW_B   = BN * PITCH;

    extern __shared__ uint32_t sm[];

    const int tid  = threadIdx.x;
    const int wid  = tid >> 5;
    const int lane = tid & 31;
    const int g    = lane >> 2;
    const int tg   = lane & 3;
    const int wm   = (wid % WARPS_M) * 64;
    const int wn   = (wid / WARPS_M) * (NT * 8);
    const int m0   = blockIdx.y * BM;
    const int n0   = blockIdx.x * BN;

    // loader: A rows {r0, r0+BM/2}; B row r0 (BM/2 == BN); 16B slot c4
    const int c4 = tid & 3;
    const int r0 = tid >> 2;               // 0..BM/2-1
    const __half* aP = A + (size_t)(m0 + r0) * lda + c4 * 8;
    const __half* wP = W + (size_t)(n0 + r0) * ldw + c4 * 8;
    const size_t aStep = (size_t)(BM / 2) * lda;

    uint32_t sbase;
    asm("{ .reg .u64 t; cvta.to.shared.u64 t, %1; cvt.u32.u64 %0, t; }" : "=r"(sbase) : "l"(sm));
    const uint32_t dOffA0 = (uint32_t)(r0 * PITCH + c4 * 4) * 4;           // bytes
    const uint32_t dOffA1 = (uint32_t)((r0 + BM / 2) * PITCH + c4 * 4) * 4;
    const uint32_t dOffB  = dOffA0;

    // ldmatrix per-lane address components (bytes, within a tile)
    // A x4: 16 rows x 2 word-offsets
    const uint32_t aLdm = (uint32_t)(((wm + (lane & 15)) * PITCH + ((lane >> 4) << 2)) * 4);
    // B x4 over an nt-pair: rows {wn+(lane&7)} (+8 for lanes>=16), word-off 4 for odd lane>>3
    const uint32_t bLdm = (uint32_t)(((wn + ((lane >> 4) << 3) + (lane & 7)) * PITCH
                                      + (((lane >> 3) & 1) << 2)) * 4);

    const int KC = K / 32;

    // prologue
#pragma unroll
    for (int s = 0; s < STAGES - 1; s++) {
        if (s < KC) {
            const uint32_t aB = sbase + (uint32_t)(s * STW_A) * 4;
            const uint32_t bB = sbase + (uint32_t)(STAGES * STW_A + s * STW_B) * 4;
            const int k0 = s * 32;
            cp16(aB + dOffA0, aP + k0);  cp16(aB + dOffA1, aP + aStep + k0);
            cp16(bB + dOffB, wP + k0);
        }
        cp_commit();
    }

    float acc[4][NT][4];
#pragma unroll
    for (int i = 0; i < 4; i++)
#pragma unroll
        for (int j = 0; j < NT; j++)
#pragma unroll
            for (int q = 0; q < 4; q++) acc[i][j][q] = 0.f;

    int bc = 0;
    int bi = STAGES - 1;

    for (int c = 0; c < KC; c++) {
        cp_wait<STAGES - 2>();
        __syncthreads();

        {
            const int cn = c + STAGES - 1;
            if (cn < KC) {
                const uint32_t aB = sbase + (uint32_t)(bi * STW_A) * 4;
                const uint32_t bB = sbase + (uint32_t)(STAGES * STW_A + bi * STW_B) * 4;
                const int k0 = cn * 32;
                cp16(aB + dOffA0, aP + k0);  cp16(aB + dOffA1, aP + aStep + k0);
                cp16(bB + dOffB, wP + k0);
            }
            cp_commit();
        }

        const uint32_t sA = sbase + (uint32_t)(bc * STW_A) * 4;
        const uint32_t sB = sbase + (uint32_t)(STAGES * STW_A + bc * STW_B) * 4;

        // ---- batch ALL fragment loads for this chunk, then all MMAs ----
        uint32_t af[2][4][4], bf[2][NT][2];
#pragma unroll
        for (int ks = 0; ks < 2; ks++) {
            const uint32_t kbB = (uint32_t)(ks * 8 * 4);   // 8 words in bytes
#pragma unroll
            for (int mt = 0; mt < 4; mt++)
                LDSM_X4(af[ks][mt][0], af[ks][mt][1], af[ks][mt][2], af[ks][mt][3],
                        sA + aLdm + (uint32_t)(mt * 16 * PITCH * 4) + kbB);
#pragma unroll
            for (int np = 0; np < NP; np++)
                LDSM_X4(bf[ks][2 * np][0], bf[ks][2 * np][1],
                        bf[ks][2 * np + 1][0], bf[ks][2 * np + 1][1],
                        sB + bLdm + (uint32_t)(np * 16 * PITCH * 4) + kbB);
        }
#pragma unroll
        for (int ks = 0; ks < 2; ks++)
#pragma unroll
            for (int mt = 0; mt < 4; mt++)
#pragma unroll
                for (int nt = 0; nt < NT; nt++)
                    mma_f16(acc[mt][nt], af[ks][mt], bf[ks][nt]);

        if (++bc == STAGES) bc = 0;
        if (++bi == STAGES) bi = 0;
    }

    // ---- epilogue ----
#pragma unroll
    for (int mt = 0; mt < 4; mt++) {
#pragma unroll
        for (int nt = 0; nt < NT; nt++) {
            const int row = m0 + wm + mt * 16 + g;
            const int col = n0 + wn + nt * 8 + 2 * tg;
            float v0 = acc[mt][nt][0], v1 = acc[mt][nt][1];
            float v2 = acc[mt][nt][2], v3 = acc[mt][nt][3];
            if (ACT == 1) {
                float b0 = bias[col], b1 = bias[col + 1];
                v0 += b0; v1 += b1; v2 += b0; v3 += b1;
                v0 = (v0 > 20.f) ? v0 : __logf(1.f + __expf(v0));
                v1 = (v1 > 20.f) ? v1 : __logf(1.f + __expf(v1));
                v2 = (v2 > 20.f) ? v2 : __logf(1.f + __expf(v2));
                v3 = (v3 > 20.f) ? v3 : __logf(1.f + __expf(v3));
            }
            *(float2*)(C + (size_t)row * ldc + col)       = make_float2(v0, v1);
            *(float2*)(C + (size_t)(row + 8) * ldc + col) = make_float2(v2, v3);
            if (DUAL) {
                *(__half2*)(Ch + (size_t)row * ldc + col)       = __floats2half2_rn(v0, v1);
                *(__half2*)(Ch + (size_t)(row + 8) * ldc + col) = __floats2half2_rn(v2, v3);
            }
        }
    }
}

// ---------------- causal depthwise conv (width 4) + SiLU (fp32 + fp16 out) ----------------
__global__ void conv_silu_kernel(const float* __restrict__ conv_w,
                                 const float* __restrict__ conv_b)
{
    int idx = blockIdx.x * blockDim.x + threadIdx.x;
    if (idx >= M_TOTAL * D_INNER) return;
    int d  = idx % D_INNER;
    int ml = idx / D_INNER;
    int l  = ml % SEQ_L;

    float acc = conv_b[d];
    const float* w = conv_w + d * D_CONV;
#pragma unroll
    for (int j = 0; j < D_CONV; j++) {
        int li = l - (D_CONV - 1) + j;
        if (li >= 0)
            acc = fmaf(w[j], g_xz[(size_t)(ml - (D_CONV - 1) + j) * (2 * D_INNER) + d], acc);
    }
    float v = acc / (1.f + __expf(-acc));   // silu
    g_xconv[idx]   = v;
    g_xconv_h[idx] = __float2half(v);
}

// ================= chunked parallel scan (unchanged from R15) =================
__global__ __launch_bounds__(256)
void scan_pass1(const float* __restrict__ A_log)
{
    const int gwarp = blockIdx.x * 8 + (threadIdx.x >> 5);
    const int lane  = threadIdx.x & 31;
    const int chunk = gwarp & (SC_NC - 1);
    const int grp   = gwarp >> 4;
    const int cw    = lane >> 2;
    const int q     = lane & 3;
    const int ch    = grp * 8 + cw;
    const int b     = ch / D_INNER;
    const int d     = ch % D_INNER;

    const float4 Alog4 = *(const float4*)(A_log + d * D_STATE + q * 4);
    const float A0 = -__expf(Alog4.x), A1 = -__expf(Alog4.y);
    const float A2 = -__expf(Alog4.z), A3 = -__expf(Alog4.w);

    const int t0 = chunk * SC_TC;
    const float* xrow  = g_xconv + (size_t)(b * SEQ_L + t0) * D_INNER + d;
    const float* dtrow = g_dt    + (size_t)(b * SEQ_L + t0) * D_INNER + d;
    const float* bcrow = g_xbc   + (size_t)(b * SEQ_L + t0) * XBC_LD;

    float h0 = 0.f, h1 = 0.f, h2 = 0.f, h3 = 0.f;
    float P0 = 1.f, P1 = 1.f, P2 = 1.f, P3 = 1.f;

#pragma unroll 4
    for (int i = 0; i < SC_TC; i++) {
        float  xv  = xrow [(size_t)i * D_INNER];
        float  dtv = dtrow[(size_t)i * D_INNER];
        float4 Bf  = *(const float4*)(bcrow + i * XBC_LD + DT_RANK + q * 4);
        float  tb  = dtv * xv;
        float a0 = fmaf(dtv, A0, 1.f);  h0 = fmaf(a0, h0, tb * Bf.x);  P0 *= a0;
        float a1 = fmaf(dtv, A1, 1.f);  h1 = fmaf(a1, h1, tb * Bf.y);  P1 *= a1;
        float a2 = fmaf(dtv, A2, 1.f);  h2 = fmaf(a2, h2, tb * Bf.z);  P2 *= a2;
        float a3 = fmaf(dtv, A3, 1.f);  h3 = fmaf(a3, h3, tb * Bf.w);  P3 *= a3;
    }

    const size_t o = ((size_t)ch * SC_NC + chunk) * D_STATE + q * 4;
    *(float4*)(g_hend  + o) = make_float4(h0, h1, h2, h3);
    *(float4*)(g_pprod + o) = make_float4(P0, P1, P2, P3);
}

__global__ __launch_bounds__(256)
void scan_pass2()
{
    const int tidg = blockIdx.x * blockDim.x + threadIdx.x;
    const int s  = tidg & (D_STATE - 1);
    const int ch = tidg >> 4;
    float h = 0.f;
#pragma unroll
    for (int c = 0; c < SC_NC; c++) {
        const size_t o = ((size_t)ch * SC_NC + c) * D_STATE + s;
        g_hin[o] = h;
        h = fmaf(g_pprod[o], h, g_hend[o]);
    }
}

__global__ __launch_bounds__(256)
void scan_pass3(const float* __restrict__ A_log, const float* __restrict__ Dp)
{
    const int gwarp = blockIdx.x * 8 + (threadIdx.x >> 5);
    const int lane  = threadIdx.x & 31;
    const int chunk = gwarp & (SC_NC - 1);
    const int grp   = gwarp >> 4;
    const int cw    = lane >> 2;
    const int q     = lane & 3;
    const int ch    = grp * 8 + cw;
    const int b     = ch / D_INNER;
    const int d     = ch % D_INNER;

    const float4 Alog4 = *(const float4*)(A_log + d * D_STATE + q * 4);
    const float A0 = -__expf(Alog4.x), A1 = -__expf(Alog4.y);
    const float A2 = -__expf(Alog4.z), A3 = -__expf(Alog4.w);
    const float Dv = Dp[d];

    const int t0 = chunk * SC_TC;
    const float* xrow  = g_xconv + (size_t)(b * SEQ_L + t0) * D_INNER + d;
    const float* dtrow = g_dt    + (size_t)(b * SEQ_L + t0) * D_INNER + d;
    const float* bcrow = g_xbc   + (size_t)(b * SEQ_L + t0) * XBC_LD;
    const float* zrow  = g_xz    + (size_t)(b * SEQ_L + t0) * (2 * D_INNER) + D_INNER + d;
    __half*      yrow  = g_y_h   + (size_t)(b * SEQ_L + t0) * D_INNER + d;

    const float4 hin = *(const float4*)(g_hin + ((size_t)ch * SC_NC + chunk) * D_STATE + q * 4);
    float h0 = hin.x, h1 = hin.y, h2 = hin.z, h3 = hin.w;

#pragma unroll 2
    for (int i = 0; i < SC_TC; i++) {
        float  xv  = xrow [(size_t)i * D_INNER];
        float  dtv = dtrow[(size_t)i * D_INNER];
        float4 Bf  = *(const float4*)(bcrow + i * XBC_LD + DT_RANK + q * 4);
        float4 Cf  = *(const float4*)(bcrow + i * XBC_LD + DT_RANK + D_STATE + q * 4);
        float  tb  = dtv * xv;
        float a0 = fmaf(dtv, A0, 1.f);  h0 = fmaf(a0, h0, tb * Bf.x);
        float a1 = fmaf(dtv, A1, 1.f);  h1 = fmaf(a1, h1, tb * Bf.y);
        float a2 = fmaf(dtv, A2, 1.f);  h2 = fmaf(a2, h2, tb * Bf.z);
        float a3 = fmaf(dtv, A3, 1.f);  h3 = fmaf(a3, h3, tb * Bf.w);

        float p = fmaf(h3, Cf.w, fmaf(h2, Cf.z, fmaf(h1, Cf.y, h0 * Cf.x)));
        p += __shfl_xor_sync(0xffffffffu, p, 1);
        p += __shfl_xor_sync(0xffffffffu, p, 2);
        if (q == 0) {
            float zv = zrow[(size_t)i * (2 * D_INNER)];
            float y  = fmaf(Dv, xv, p);
            y *= zv / (1.f + __expf(-zv));
            yrow[(size_t)i * D_INNER] = __float2half(y);
        }
    }
}

// ---------------- launch ----------------
extern "C" void kernel_launch(void* const* d_in, const int* in_sizes, int n_in,
                              void* d_out, int out_size)
{
    const float* x          = (const float*)d_in[0];
    const float* in_proj_w  = (const float*)d_in[1];
    const float* conv_w     = (const float*)d_in[2];
    const float* conv_b     = (const float*)d_in[3];
    const float* A_log      = (const float*)d_in[4];
    const float* Dp         = (const float*)d_in[5];
    const float* dt_proj_w  = (const float*)d_in[6];
    const float* dt_proj_b  = (const float*)d_in[7];
    const float* x_proj_w   = (const float*)d_in[8];
    const float* B_proj_w   = (const float*)d_in[9];
    const float* C_proj_w   = (const float*)d_in[10];
    const float* out_proj_w = (const float*)d_in[11];
    float* out = (float*)d_out;

    // resolve scratch addresses
    float  *xz, *xbc, *dt, *wcat;
    __half *xconv_h, *xbc_h, *y_h, *wcat_h, *x_h, *win_h, *wdt_h, *wout_h;
    cudaGetSymbolAddress((void**)&xz,      g_xz);
    cudaGetSymbolAddress((void**)&xbc,     g_xbc);
    cudaGetSymbolAddress((void**)&dt,      g_dt);
    cudaGetSymbolAddress((void**)&wcat,    g_wcat);
    cudaGetSymbolAddress((void**)&xconv_h, g_xconv_h);
    cudaGetSymbolAddress((void**)&xbc_h,   g_xbc_h);
    cudaGetSymbolAddress((void**)&y_h,     g_y_h);
    cudaGetSymbolAddress((void**)&wcat_h,  g_wcat_h);
    cudaGetSymbolAddress((void**)&x_h,     g_x_h);
    cudaGetSymbolAddress((void**)&win_h,   g_win_h);
    cudaGetSymbolAddress((void**)&wdt_h,   g_wdt_h);
    cudaGetSymbolAddress((void**)&wout_h,  g_wout_h);

    cudaFuncSetAttribute(tc_gemm<256, 0, 0>, cudaFuncAttributeMaxDynamicSharedMemorySize, GCfg<256>::SMEM);
    cudaFuncSetAttribute(tc_gemm<256, 1, 0>, cudaFuncAttributeMaxDynamicSharedMemorySize, GCfg<256>::SMEM);
    cudaFuncSetAttribute(tc_gemm<128, 0, 1>, cudaFuncAttributeMaxDynamicSharedMemorySize, GCfg<128>::SMEM);

    // pack [x_proj_w; B_proj_w; C_proj_w] -> g_wcat rows 0..95 (96..127 zero)
    cudaMemcpyToSymbolAsync(g_wcat, x_proj_w, (size_t)DT_RANK * D_INNER * sizeof(float),
                            0, cudaMemcpyDeviceToDevice, 0);
    cudaMemcpyToSymbolAsync(g_wcat, B_proj_w, (size_t)D_STATE * D_INNER * sizeof(float),
                            (size_t)DT_RANK * D_INNER * sizeof(float), cudaMemcpyDeviceToDevice, 0);
    cudaMemcpyToSymbolAsync(g_wcat, C_proj_w, (size_t)D_STATE * D_INNER * sizeof(float),
                            (size_t)(DT_RANK + D_STATE) * D_INNER * sizeof(float), cudaMemcpyDeviceToDevice, 0);

    // fp16 conversions of GEMM operands
    {
        auto cvt = [](const float* s, __half* dptr, size_t n) {
            int n4 = (int)(n / 4);
            cvt_f16_kernel<<<(n4 + 255) / 256, 256>>>(s, dptr, n4);
        };
        cvt(x,          x_h,    (size_t)M_TOTAL * D_MODEL);
        cvt(in_proj_w,  win_h,  (size_t)2 * D_INNER * D_MODEL);
        cvt(dt_proj_w,  wdt_h,  (size_t)D_INNER * DT_RANK);
        cvt(out_proj_w, wout_h, (size_t)D_MODEL * D_INNER);
        cvt(wcat,       wcat_h, (size_t)XBC_LD * D_INNER);
    }

    // 1) in_proj: xz = x @ in_proj_w^T   (M=4096, N=4096, K=1024) [BM=256, BN=128]
    {
        dim3 grid(2 * D_INNER / 128, M_TOTAL / 256);
        tc_gemm<256, 0, 0><<<grid, 512, GCfg<256>::SMEM>>>(
            x_h, D_MODEL, win_h, D_MODEL, nullptr, xz, nullptr, 2 * D_INNER, D_MODEL);
    }

    // 2) causal depthwise conv + silu -> g_xconv (fp32) + g_xconv_h (fp16)
    {
        int n = M_TOTAL * D_INNER;
        conv_silu_kernel<<<(n + 255) / 256, 256>>>(conv_w, conv_b);
    }

    // 3) fused x/B/C projection: xbc = xconv @ wcat^T (M=4096, N=128, K=2048) [BM=128, BN=64, dual]
    {
        dim3 grid(XBC_LD / 64, M_TOTAL / 128);
        tc_gemm<128, 0, 1><<<grid, 256, GCfg<128>::SMEM>>>(
            xconv_h, D_INNER, wcat_h, D_INNER, nullptr, xbc, xbc_h, XBC_LD, D_INNER);
    }

    // 4) dt = softplus(xbc[:, :64] @ dt_proj_w^T + dt_proj_b)  (N=2048, K=64) [BM=256, BN=128]
    {
        dim3 grid(D_INNER / 128, M_TOTAL / 256);
        tc_gemm<256, 1, 0><<<grid, 512, GCfg<256>::SMEM>>>(
            xbc_h, XBC_LD, wdt_h, DT_RANK, dt_proj_b, dt, nullptr, D_INNER, DT_RANK);
    }

    // 5) chunked parallel scan
    scan_pass1<<<1024, 256>>>(A_log);
    scan_pass2<<<256, 256>>>();
    scan_pass3<<<1024, 256>>>(A_log, Dp);

    // 6) out = y @ out_proj_w^T   (M=4096, N=1024, K=2048) [BM=256, BN=128]
    {
        dim3 grid(D_MODEL / 128, M_TOTAL / 256);
        tc_gemm<256, 0, 0><<<grid, 512, GCfg<256>::SMEM>>>(
            y_h, D_INNER, wout_h, D_INNER, nullptr, out, nullptr, D_MODEL, D_INNER);
    }
}